// round 2
// baseline (speedup 1.0000x reference)
#include <cuda_runtime.h>

#define BB   16
#define CINC 256
#define COUT 128
#define HH   64
#define WW   64
#define OH   128
#define OW   128

typedef unsigned long long u64;

// Per-sample, phase/tap-reordered, DUPLICATED weights:
// [b][phase(4)][ic][tap(4)][oc][2]  (each weight stored twice -> LDS.64 broadcast pair)
__device__ float g_w[BB * 4 * CINC * 4 * COUT * 2];   // 64 MB scratch (static, allowed)

__device__ __forceinline__ u64 ffma2(u64 a, u64 b, u64 c) {
    u64 d;
    asm("fma.rn.f32x2 %0, %1, %2, %3;" : "=l"(d) : "l"(a), "l"(b), "l"(c));
    return d;
}
__device__ __forceinline__ u64 pk(float lo, float hi) {
    u64 d;
    asm("mov.b64 %0, {%1, %2};" : "=l"(d) : "f"(lo), "f"(hi));
    return d;
}

// ---------------------------------------------------------------------------
// Kernel 1: weight synthesis.  One block per ic (256 blocks, 256 threads).
// Writes duplicated-pair layout.
// ---------------------------------------------------------------------------
__global__ __launch_bounds__(256) void synth_kernel(
    const float* __restrict__ feature,            // (16,4)
    const float* __restrict__ w0,                 // (256,128,4,4)
    const float* __restrict__ tb, const float* __restrict__ tq,
    const float* __restrict__ tn, const float* __restrict__ tx,
    const float* __restrict__ mb, const float* __restrict__ mq,
    const float* __restrict__ mn, const float* __restrict__ mx)
{
    __shared__ float sf[64];
    __shared__ float buf[2048];                   // [phase][tap][oc] for one (b, ic)

    const int ic = blockIdx.x;
    const int t  = threadIdx.x;
    if (t < 64) sf[t] = feature[t];
    __syncthreads();

    float base[8], ub[8], uq[8], un[8], ux[8];
    int   sidx[8];
    const int off = ic * 2048;

#pragma unroll
    for (int j = 0; j < 8; j++) {
        const int idx = t + 256 * j;              // = oc*16 + ky*4 + kx
        const int oc  = idx >> 4;
        const int kk  = idx & 15;
        const int ky  = kk >> 2, kx = kk & 3;
        const float mB = mb[ic * COUT + oc], mQ = mq[ic * COUT + oc];
        const float mN = mn[ic * COUT + oc], mX = mx[ic * COUT + oc];
        base[j] = w0[off + idx];
        ub[j] = tb[off + idx] * mB;
        uq[j] = tq[off + idx] * mQ;
        un[j] = tn[off + idx] * mN;
        ux[j] = tx[off + idx] * mX;
        const int py = 1 - (ky & 1), px = 1 - (kx & 1);
        const int tap = (ky >> 1) * 2 + (kx >> 1);
        sidx[j] = (py * 2 + px) * 512 + tap * 128 + oc;
    }

    for (int b = 0; b < BB; b++) {
        const float f0 = sf[b * 4 + 0], f1 = sf[b * 4 + 1];
        const float f2 = sf[b * 4 + 2], f3 = sf[b * 4 + 3];
#pragma unroll
        for (int j = 0; j < 8; j++)
            buf[sidx[j]] = base[j] + f0 * ub[j] + f1 * uq[j] + f2 * un[j] + f3 * ux[j];
        __syncthreads();
#pragma unroll
        for (int p = 0; p < 4; p++) {
            float2* gp = reinterpret_cast<float2*>(
                g_w + (size_t)(((b * 4 + p) * CINC + ic)) * 1024);
#pragma unroll
            for (int j = 0; j < 2; j++) {
                const int e = t + j * 256;        // 0..511
                const float v = buf[p * 512 + e];
                gp[e] = make_float2(v, v);        // duplicated pair, STG.64 coalesced
            }
        }
        __syncthreads();
    }
}

// ---------------------------------------------------------------------------
// Kernel 2: phase-separated implicit-GEMM transposed conv, packed f32x2 FMA.
// Grid: (ytile=16, phase=4, b=16).  Block tile: 128 oc x (4 rows x 64 cols).
// Thread tile: 8 oc x 8 pixel-pairs (64 f32x2 accumulators = 128 floats).
// ---------------------------------------------------------------------------
__global__ __launch_bounds__(256) void deconv_kernel(
    const float* __restrict__ x,                  // (16,256,64,64)
    const float* __restrict__ bias,               // (128,)
    const float* __restrict__ prelu_a,            // (1,)
    float* __restrict__ out)                      // (16,128,128,128)
{
    __shared__ float sw[8 * 4 * 256];             // [ic_local*4+tap][oc*2]  32 KB (dup pairs)
    __shared__ float sx[8 * 5 * 68];              // [ic_local][row(5)][col(65 pad 68)]

    const int ytile = blockIdx.x;                 // 0..15
    const int phase = blockIdx.y;                 // 0..3
    const int b     = blockIdx.z;                 // 0..15
    const int py = phase >> 1, px = phase & 1;

    const int t  = threadIdx.x;
    const int to = t >> 4;                        // oc group: oc_base = to*8
    const int tp = t & 15;
    const int r  = tp >> 2;                       // row within tile (0..3)
    const int c0 = (tp & 3) * 16;                 // col segment start

    const int y0    = ytile * 4;
    const int dymin = (py == 0) ? -1 : 0;
    const int dxmin = (px == 0) ? -1 : 0;

    u64 acc[8][8];
#pragma unroll
    for (int o = 0; o < 8; o++)
#pragma unroll
        for (int j = 0; j < 8; j++) acc[o][j] = 0ull;

    const float* gw = g_w + (size_t)((b * 4 + phase) * CINC) * 1024;
    const float* xb = x + (size_t)b * CINC * HH * WW;

    for (int ic0 = 0; ic0 < CINC; ic0 += 8) {
        // --- stage duplicated weights: 8192 contiguous floats = 2048 float4 ---
        const float4* gw4 = reinterpret_cast<const float4*>(gw + ic0 * 1024);
        float4* sw4 = reinterpret_cast<float4*>(sw);
#pragma unroll
        for (int j = 0; j < 8; j++) sw4[t + 256 * j] = gw4[t + 256 * j];

        // --- stage x tile with zero-filled halo: 8 ic x 5 rows x 65 cols ---
        for (int idx = t; idx < 8 * 5 * 65; idx += 256) {
            const int i  = idx % 65;
            const int jj = (idx / 65) % 5;
            const int ii = idx / 325;
            const int gy = y0 + dymin + jj;
            const int gx = dxmin + i;
            float v = 0.f;
            if ((unsigned)gy < 64u && (unsigned)gx < 64u)
                v = xb[(ic0 + ii) * (HH * WW) + gy * WW + gx];
            sx[(ii * 5 + jj) * 68 + i] = v;
        }
        __syncthreads();

#pragma unroll 2
        for (int il = 0; il < 8; il++) {
#pragma unroll
            for (int tky = 0; tky < 2; tky++) {
                // 17 x values for this row
                float xr[17];
                const float* sxr = sx + (il * 5 + (r + 1 - tky)) * 68 + c0;
#pragma unroll
                for (int q = 0; q < 4; q++) {
                    const float4 v4 = *reinterpret_cast<const float4*>(sxr + 4 * q);
                    xr[4 * q + 0] = v4.x; xr[4 * q + 1] = v4.y;
                    xr[4 * q + 2] = v4.z; xr[4 * q + 3] = v4.w;
                }
                xr[16] = sxr[16];

                // aligned pairs (tkx=1 path) and shifted pairs (tkx=0 path)
                u64 pa[8], ps[8];
#pragma unroll
                for (int j = 0; j < 8; j++) {
                    pa[j] = pk(xr[2 * j],     xr[2 * j + 1]);
                    ps[j] = pk(xr[2 * j + 1], xr[2 * j + 2]);
                }

#pragma unroll
                for (int tkx = 0; tkx < 2; tkx++) {
                    const int tap = tky * 2 + tkx;
                    const u64* swp = reinterpret_cast<const u64*>(
                        sw + (il * 4 + tap) * 256) + to * 8;
                    u64 wv[8];
#pragma unroll
                    for (int o = 0; o < 8; o++) wv[o] = swp[o];   // LDS.64 (w,w)

                    const u64* xp = tkx ? pa : ps;
#pragma unroll
                    for (int o = 0; o < 8; o++)
#pragma unroll
                        for (int j = 0; j < 8; j++)
                            acc[o][j] = ffma2(wv[o], xp[j], acc[o][j]);
                }
            }
        }
        __syncthreads();
    }

    // --- epilogue: bias + PReLU, direct store ---
    const float pa  = prelu_a[0];
    const int   ocb = to * 8;
    const int   oy  = 2 * (y0 + r) + py;
#pragma unroll
    for (int o = 0; o < 8; o++) {
        const float bz = bias[ocb + o];
        float* orow = out + (((size_t)(b * COUT + ocb + o)) * OH + oy) * OW + px;
#pragma unroll
        for (int j = 0; j < 8; j++) {
            float lo = __uint_as_float((unsigned)(acc[o][j] & 0xFFFFFFFFull));
            float hi = __uint_as_float((unsigned)(acc[o][j] >> 32));
            lo += bz; hi += bz;
            lo = (lo >= 0.f) ? lo : pa * lo;
            hi = (hi >= 0.f) ? hi : pa * hi;
            orow[2 * (c0 + 2 * j)]     = lo;
            orow[2 * (c0 + 2 * j + 1)] = hi;
        }
    }
}

// ---------------------------------------------------------------------------
extern "C" void kernel_launch(void* const* d_in, const int* in_sizes, int n_in,
                              void* d_out, int out_size)
{
    const float* x       = (const float*)d_in[0];
    const float* feature = (const float*)d_in[1];
    const float* weight  = (const float*)d_in[2];
    const float* tb      = (const float*)d_in[3];
    const float* tq      = (const float*)d_in[4];
    const float* tn      = (const float*)d_in[5];
    const float* tx      = (const float*)d_in[6];
    const float* mb      = (const float*)d_in[7];
    const float* mq      = (const float*)d_in[8];
    const float* mn      = (const float*)d_in[9];
    const float* mx      = (const float*)d_in[10];
    const float* bias    = (const float*)d_in[11];
    const float* prelu_a = (const float*)d_in[12];
    float* out = (float*)d_out;

    synth_kernel<<<CINC, 256>>>(feature, weight, tb, tq, tn, tx, mb, mq, mn, mx);

    dim3 grid(16, 4, 16);
    deconv_kernel<<<grid, 256>>>(x, bias, prelu_a, out);
}

// round 5
// speedup vs baseline: 3.2181x; 3.2181x over previous
#include <cuda_runtime.h>
#include <cuda_bf16.h>
#include <cstdint>

#define BB   16
#define CINC 256
#define COUTC 128
#define HH   64
#define WW   64
#define OH   128
#define OW   128

// ===========================================================================
// Device scratch (static allocation — allowed)
// g_wi: synthesized split weights, [plane = ((b*4+ph)*4+tap)*2+prec][ic 256][oc 128] bf16
// g_wt: transposed,                [plane][oc 128][ic 256] bf16
// g_xt: transposed input + halo,   [b][prec][yy 66][xx 66][ic 256] bf16
// ===========================================================================
__device__ __align__(16) unsigned short g_wi[16u * 4 * 4 * 2 * 256 * 128];
__device__ __align__(16) unsigned short g_wt[16u * 4 * 4 * 2 * 256 * 128];
__device__ __align__(16) unsigned short g_xt[16u * 2 * 66 * 66 * 256];

__device__ __forceinline__ unsigned short bf16_of(float f) {
    return __bfloat16_as_ushort(__float2bfloat16_rn(f));
}
__device__ __forceinline__ uint32_t smem_u32(const void* p) {
    uint32_t a;
    asm("{ .reg .u64 tmp; cvta.to.shared.u64 tmp, %1; cvt.u32.u64 %0, tmp; }"
        : "=r"(a) : "l"(p));
    return a;
}
__device__ __forceinline__ void ldm_x4(uint32_t* r, uint32_t addr) {
    asm volatile("ldmatrix.sync.aligned.m8n8.x4.shared.b16 {%0,%1,%2,%3}, [%4];"
                 : "=r"(r[0]), "=r"(r[1]), "=r"(r[2]), "=r"(r[3]) : "r"(addr));
}
__device__ __forceinline__ void mma_bf16(float* c, const uint32_t* a,
                                         uint32_t b0, uint32_t b1) {
    asm volatile("mma.sync.aligned.m16n8k16.row.col.f32.bf16.bf16.f32 "
                 "{%0,%1,%2,%3}, {%4,%5,%6,%7}, {%8,%9}, {%0,%1,%2,%3};"
                 : "+f"(c[0]), "+f"(c[1]), "+f"(c[2]), "+f"(c[3])
                 : "r"(a[0]), "r"(a[1]), "r"(a[2]), "r"(a[3]), "r"(b0), "r"(b1));
}

// ===========================================================================
// Kernel 1: weight synthesis + hi/lo split.  Block per ic.
// ===========================================================================
__global__ __launch_bounds__(256) void synth_kernel(
    const float* __restrict__ feature, const float* __restrict__ w0,
    const float* __restrict__ tb, const float* __restrict__ tq,
    const float* __restrict__ tn, const float* __restrict__ tx,
    const float* __restrict__ mb, const float* __restrict__ mq,
    const float* __restrict__ mn, const float* __restrict__ mx)
{
    __shared__ float sf[64];
    __shared__ float buf[2048];                   // [phase][tap][oc] for one (b, ic)

    const int ic = blockIdx.x;
    const int t  = threadIdx.x;
    if (t < 64) sf[t] = feature[t];
    __syncthreads();

    float base[8], ub[8], uq[8], un[8], ux[8];
    int   sidx[8];
    const int off = ic * 2048;

#pragma unroll
    for (int j = 0; j < 8; j++) {
        const int idx = t + 256 * j;              // = oc*16 + ky*4 + kx
        const int oc  = idx >> 4;
        const int kk  = idx & 15;
        const int ky  = kk >> 2, kx = kk & 3;
        const float mB = mb[ic * COUTC + oc], mQ = mq[ic * COUTC + oc];
        const float mN = mn[ic * COUTC + oc], mX = mx[ic * COUTC + oc];
        base[j] = w0[off + idx];
        ub[j] = tb[off + idx] * mB;
        uq[j] = tq[off + idx] * mQ;
        un[j] = tn[off + idx] * mN;
        ux[j] = tx[off + idx] * mX;
        const int py = 1 - (ky & 1), px = 1 - (kx & 1);
        const int tap = (ky >> 1) * 2 + (kx >> 1);
        sidx[j] = (py * 2 + px) * 512 + tap * 128 + oc;
    }

    for (int b = 0; b < BB; b++) {
        const float f0 = sf[b * 4 + 0], f1 = sf[b * 4 + 1];
        const float f2 = sf[b * 4 + 2], f3 = sf[b * 4 + 3];
#pragma unroll
        for (int j = 0; j < 8; j++)
            buf[sidx[j]] = base[j] + f0 * ub[j] + f1 * uq[j] + f2 * un[j] + f3 * ux[j];
        __syncthreads();
#pragma unroll
        for (int j = 0; j < 8; j++) {
            const int e = t + 256 * j;            // phase*512 + tap*128 + oc
            const float w = buf[e];
            const unsigned short hi = bf16_of(w);
            const float fh = __bfloat162float(__ushort_as_bfloat16(hi));
            const unsigned short lo = bf16_of(w - fh);
            const int plane2 = b * 16 + (e >> 7); // (b*4+phase)*4+tap
            g_wi[(size_t)(plane2 * 2 + 0) * 32768 + ic * 128 + (e & 127)] = hi;
            g_wi[(size_t)(plane2 * 2 + 1) * 32768 + ic * 128 + (e & 127)] = lo;
        }
        __syncthreads();
    }
}

// ===========================================================================
// Kernel 2: weight transpose [ic][oc] -> [oc][ic] per plane (512 planes)
// ===========================================================================
__global__ __launch_bounds__(256) void transposeW_kernel()
{
    __shared__ unsigned int sm[64][65];
    const int plane = blockIdx.x;
    const int t = threadIdx.x;
    const unsigned int* src = reinterpret_cast<const unsigned int*>(g_wi) + (size_t)plane * 16384;
    unsigned int*       dst = reinterpret_cast<unsigned int*>(g_wt) + (size_t)plane * 16384;

    for (int ic0 = 0; ic0 < 256; ic0 += 64) {
        __syncthreads();
#pragma unroll
        for (int j = 0; j < 16; j++) {
            const int idx = t + 256 * j;          // 4096 u32
            const int icl = idx >> 6, oc2 = idx & 63;
            sm[icl][oc2] = src[(ic0 + icl) * 64 + oc2];
        }
        __syncthreads();
#pragma unroll
        for (int j = 0; j < 16; j++) {
            const int idx = t + 256 * j;
            const int oc = idx >> 5, icp = idx & 31;
            const unsigned int w0v = sm[icp * 2][oc >> 1];
            const unsigned int w1v = sm[icp * 2 + 1][oc >> 1];
            const int sh = (oc & 1) * 16;
            const unsigned int r = ((w0v >> sh) & 0xffffu) | (((w1v >> sh) & 0xffffu) << 16);
            dst[oc * 128 + (ic0 >> 1) + icp] = r;
        }
    }
}

// ===========================================================================
// Kernel 3: zero X_t (halo stays zero)
// ===========================================================================
__global__ void zero_xt_kernel()
{
    const size_t i = (size_t)blockIdx.x * 256 + threadIdx.x;
    reinterpret_cast<float4*>(g_xt)[i] = make_float4(0.f, 0.f, 0.f, 0.f);
}

// ===========================================================================
// Kernel 4: x transpose + split: x[b][ic][y][x] -> g_xt[b][prec][y+1][x+1][ic]
// ===========================================================================
__global__ __launch_bounds__(256) void transposeX_kernel(const float* __restrict__ x)
{
    __shared__ float sm[128][65];
    const int bx = blockIdx.x;
    const int b = bx >> 6, y = bx & 63;
    const int t = threadIdx.x;

    for (int ic0 = 0; ic0 < 256; ic0 += 128) {
        __syncthreads();
#pragma unroll
        for (int j = 0; j < 32; j++) {
            const int idx = t + 256 * j;          // 8192
            const int icl = idx >> 6, xc = idx & 63;
            sm[icl][xc] = x[((size_t)(b * 256 + ic0 + icl) * 64 + y) * 64 + xc];
        }
        __syncthreads();
#pragma unroll
        for (int j = 0; j < 16; j++) {
            const int idx = t + 256 * j;          // 4096 u32
            const int xc = idx >> 6, icp = idx & 63;
            const float f0 = sm[icp * 2][xc], f1 = sm[icp * 2 + 1][xc];
            const unsigned short h0 = bf16_of(f0), h1 = bf16_of(f1);
            const float fh0 = __bfloat162float(__ushort_as_bfloat16(h0));
            const float fh1 = __bfloat162float(__ushort_as_bfloat16(h1));
            const unsigned short l0 = bf16_of(f0 - fh0), l1 = bf16_of(f1 - fh1);
            const unsigned int hw = (unsigned int)h0 | ((unsigned int)h1 << 16);
            const unsigned int lw = (unsigned int)l0 | ((unsigned int)l1 << 16);
            const size_t rh = (((size_t)(b * 2 + 0) * 66 + (y + 1)) * 66 + (xc + 1));
            const size_t rl = (((size_t)(b * 2 + 1) * 66 + (y + 1)) * 66 + (xc + 1));
            unsigned int* xt32 = reinterpret_cast<unsigned int*>(g_xt);
            xt32[rh * 128 + (ic0 >> 1) + icp] = hw;
            xt32[rl * 128 + (ic0 >> 1) + icp] = lw;
        }
    }
}

// ===========================================================================
// Kernel 5: mma.sync bf16 GEMM.  Grid (ytile 16, phase 4, b 16), 256 thr.
// CTA tile: 128 oc x 256 px (4 rows x 64 cols).  Warp tile 64x64.
// smem: sx [prec2][325 px][80B rows, 32ic], sA [8 tiles][128 oc][80B rows].
// ===========================================================================
#define SX_PREC_STRIDE 26240                      // 325*80 rounded to 128
#define SX_BYTES (2 * SX_PREC_STRIDE)             // 52480
#define SA_OFF   SX_BYTES
#define SA_TILE  10240                            // 128*80
#define SMEM_BYTES (SA_OFF + 8 * SA_TILE + 256)   // 134656

__global__ __launch_bounds__(256)
void gemm_kernel(const float* __restrict__ bias,
                 const float* __restrict__ prelu_a,
                 float* __restrict__ out)
{
    extern __shared__ char smem[];
    char* sxc = smem;
    char* sac = smem + SA_OFF;
    const uint32_t sx_u = smem_u32(smem);
    const uint32_t sa_u = sx_u + SA_OFF;

    const int t = threadIdx.x, wid = t >> 5, lane = t & 31;
    const int ytile = blockIdx.x, phase = blockIdx.y, b = blockIdx.z;
    const int py = phase >> 1, px = phase & 1;
    const int y0 = ytile * 4;
    const int dymin = (py == 0) ? -1 : 0;
    const int dxmin = (px == 0) ? -1 : 0;

    const int warp_m = wid & 1;                   // m_base = warp_m*64
    const int warp_n = wid >> 1;                  // output row within tile (0..3)
    const int m_base = warp_m * 64;

    // ldmatrix per-lane addressing
    const int a_row  = lane & 15;
    const int a_coff = lane >> 4;                 // 0/1 -> k8 half
    const int b_row  = ((lane >> 4) & 1) * 8 + (lane & 7);
    const int b_coff = (lane >> 3) & 1;

    float acc[4][8][4];
#pragma unroll
    for (int ma = 0; ma < 4; ma++)
#pragma unroll
        for (int j = 0; j < 8; j++)
#pragma unroll
            for (int q = 0; q < 4; q++) acc[ma][j][q] = 0.f;

    const char* gxt = reinterpret_cast<const char*>(g_xt);
    const char* gwt = reinterpret_cast<const char*>(g_wt);

    for (int ic0 = 0; ic0 < 256; ic0 += 32) {
        __syncthreads();
        // ---- stage sx: [prec2][325 px (5 rows x 65 cols)][4 chunks of 16B]
        for (int i = t; i < 2600; i += 256) {
            const int prec = (i >= 1300) ? 1 : 0;
            const int j = i - prec * 1300;
            const int p = j >> 2, c = j & 3;
            const int jj = p / 65, xi = p - jj * 65;
            const int yy = y0 + dymin + jj + 1;    // in [0,65]
            const int xx = dxmin + xi + 1;         // in [0,65]
            const float4 v = *reinterpret_cast<const float4*>(
                gxt + (((size_t)(b * 2 + prec) * 66 + yy) * 66 + xx) * 512
                    + ic0 * 2 + c * 16);
            *reinterpret_cast<float4*>(sxc + prec * SX_PREC_STRIDE + p * 80 + c * 16) = v;
        }
        // ---- stage A: 8 tiles [tap2x2][aprec] of [128 oc][32 ic]
        for (int i = t; i < 4096; i += 256) {
            const int c = i & 3, oc = (i >> 2) & 127, tile = i >> 9;
            const int tap = tile >> 1, aprec = tile & 1;
            const int plane = ((b * 4 + phase) * 4 + tap) * 2 + aprec;
            const float4 v = *reinterpret_cast<const float4*>(
                gwt + (size_t)plane * 65536 + oc * 512 + ic0 * 2 + c * 16);
            *reinterpret_cast<float4*>(sac + tile * SA_TILE + oc * 80 + c * 16) = v;
        }
        __syncthreads();

#pragma unroll
        for (int kk = 0; kk < 2; kk++) {
#pragma unroll
            for (int tap = 0; tap < 4; tap++) {
                const int tky = tap >> 1, tkx = tap & 1;
                const int pbase = (warp_n + 1 - tky) * 65 + (1 - tkx);
                const int kcol = (kk * 2) * 16;

                uint32_t ah[4][4], bh[4][4];
#pragma unroll
                for (int ma = 0; ma < 4; ma++)
                    ldm_x4(ah[ma], sa_u + (tap * 2 + 0) * SA_TILE
                           + (m_base + ma * 16 + a_row) * 80 + kcol + a_coff * 16);
#pragma unroll
                for (int nb = 0; nb < 4; nb++)
                    ldm_x4(bh[nb], sx_u + 0 * SX_PREC_STRIDE
                           + (pbase + nb * 16 + b_row) * 80 + kcol + b_coff * 16);
#pragma unroll
                for (int ma = 0; ma < 4; ma++)
#pragma unroll
                    for (int j = 0; j < 8; j++)
                        mma_bf16(acc[ma][j], ah[ma], bh[j >> 1][(j & 1) * 2],
                                 bh[j >> 1][(j & 1) * 2 + 1]);

                // lo(A) x hi(B)
                {
                    uint32_t al[4][4];
#pragma unroll
                    for (int ma = 0; ma < 4; ma++)
                        ldm_x4(al[ma], sa_u + (tap * 2 + 1) * SA_TILE
                               + (m_base + ma * 16 + a_row) * 80 + kcol + a_coff * 16);
#pragma unroll
                    for (int ma = 0; ma < 4; ma++)
#pragma unroll
                        for (int j = 0; j < 8; j++)
                            mma_bf16(acc[ma][j], al[ma], bh[j >> 1][(j & 1) * 2],
                                     bh[j >> 1][(j & 1) * 2 + 1]);
                }
                // hi(A) x lo(B)
                {
                    uint32_t bl[4][4];
#pragma unroll
                    for (int nb = 0; nb < 4; nb++)
                        ldm_x4(bl[nb], sx_u + 1 * SX_PREC_STRIDE
                               + (pbase + nb * 16 + b_row) * 80 + kcol + b_coff * 16);
#pragma unroll
                    for (int ma = 0; ma < 4; ma++)
#pragma unroll
                        for (int j = 0; j < 8; j++)
                            mma_bf16(acc[ma][j], ah[ma], bl[j >> 1][(j & 1) * 2],
                                     bl[j >> 1][(j & 1) * 2 + 1]);
                }
            }
        }
    }

    // ---- epilogue: bias + PReLU, scattered stride-2 stores
    const float pa = prelu_a[0];
    const int oy = 2 * (y0 + warp_n) + py;
#pragma unroll
    for (int ma = 0; ma < 4; ma++) {
        const int m0 = m_base + ma * 16 + (lane >> 2);
        const float bz0 = bias[m0];
        const float bz1 = bias[m0 + 8];
        float* r0 = out + ((size_t)(b * COUTC + m0) * OH + oy) * OW + px;
        float* r1 = out + ((size_t)(b * COUTC + m0 + 8) * OH + oy) * OW + px;
#pragma unroll
        for (int j = 0; j < 8; j++) {
            const int col = j * 8 + (lane & 3) * 2;
            float v0 = acc[ma][j][0] + bz0;
            float v1 = acc[ma][j][1] + bz0;
            float v2 = acc[ma][j][2] + bz1;
            float v3 = acc[ma][j][3] + bz1;
            v0 = (v0 >= 0.f) ? v0 : pa * v0;
            v1 = (v1 >= 0.f) ? v1 : pa * v1;
            v2 = (v2 >= 0.f) ? v2 : pa * v2;
            v3 = (v3 >= 0.f) ? v3 : pa * v3;
            r0[2 * col]       = v0;
            r0[2 * (col + 1)] = v1;
            r1[2 * col]       = v2;
            r1[2 * (col + 1)] = v3;
        }
    }
}

// ===========================================================================
extern "C" void kernel_launch(void* const* d_in, const int* in_sizes, int n_in,
                              void* d_out, int out_size)
{
    const float* x       = (const float*)d_in[0];
    const float* feature = (const float*)d_in[1];
    const float* weight  = (const float*)d_in[2];
    const float* tb      = (const float*)d_in[3];
    const float* tq      = (const float*)d_in[4];
    const float* tn      = (const float*)d_in[5];
    const float* tx      = (const float*)d_in[6];
    const float* mb      = (const float*)d_in[7];
    const float* mq      = (const float*)d_in[8];
    const float* mn      = (const float*)d_in[9];
    const float* mx      = (const float*)d_in[10];
    const float* bias    = (const float*)d_in[11];
    const float* prelu_a = (const float*)d_in[12];
    float* out = (float*)d_out;

    cudaFuncSetAttribute(gemm_kernel,
                         cudaFuncAttributeMaxDynamicSharedMemorySize, SMEM_BYTES);

    zero_xt_kernel<<<17424, 256>>>();
    transposeX_kernel<<<1024, 256>>>(x);
    synth_kernel<<<256, 256>>>(feature, weight, tb, tq, tn, tx, mb, mq, mn, mx);
    transposeW_kernel<<<512, 256>>>();

    dim3 grid(16, 4, 16);
    gemm_kernel<<<grid, 256, SMEM_BYTES>>>(bias, prelu_a, out);
}

// round 6
// speedup vs baseline: 3.7631x; 1.1693x over previous
#include <cuda_runtime.h>
#include <cuda_bf16.h>
#include <cstdint>

#define BB   16
#define CINC 256
#define COUTC 128
#define HH   64
#define WW   64
#define OH   128
#define OW   128

// ===========================================================================
// Device scratch (static allocation — allowed)
// g_wi: synthesized split weights, [plane = ((b*4+ph)*4+tap)*2+prec][ic 256][oc 128] bf16
// g_wt: transposed,                [plane][oc 128][ic 256] bf16
// g_xt: transposed input + halo,   [b][prec][yy 66][xx 66][ic 256] bf16
// ===========================================================================
__device__ __align__(16) unsigned short g_wi[16u * 4 * 4 * 2 * 256 * 128];
__device__ __align__(16) unsigned short g_wt[16u * 4 * 4 * 2 * 256 * 128];
__device__ __align__(16) unsigned short g_xt[16u * 2 * 66 * 66 * 256];

__device__ __forceinline__ unsigned short bf16_of(float f) {
    return __bfloat16_as_ushort(__float2bfloat16_rn(f));
}
__device__ __forceinline__ uint32_t smem_u32(const void* p) {
    uint32_t a;
    asm("{ .reg .u64 tmp; cvta.to.shared.u64 tmp, %1; cvt.u32.u64 %0, tmp; }"
        : "=r"(a) : "l"(p));
    return a;
}
__device__ __forceinline__ void ldm_x4(uint32_t* r, uint32_t addr) {
    asm volatile("ldmatrix.sync.aligned.m8n8.x4.shared.b16 {%0,%1,%2,%3}, [%4];"
                 : "=r"(r[0]), "=r"(r[1]), "=r"(r[2]), "=r"(r[3]) : "r"(addr));
}
__device__ __forceinline__ void mma_bf16(float* c, const uint32_t* a,
                                         uint32_t b0, uint32_t b1) {
    asm volatile("mma.sync.aligned.m16n8k16.row.col.f32.bf16.bf16.f32 "
                 "{%0,%1,%2,%3}, {%4,%5,%6,%7}, {%8,%9}, {%0,%1,%2,%3};"
                 : "+f"(c[0]), "+f"(c[1]), "+f"(c[2]), "+f"(c[3])
                 : "r"(a[0]), "r"(a[1]), "r"(a[2]), "r"(a[3]), "r"(b0), "r"(b1));
}
__device__ __forceinline__ void cp16(uint32_t saddr, const void* g) {
    asm volatile("cp.async.cg.shared.global [%0], [%1], 16;"
                 :: "r"(saddr), "l"(g) : "memory");
}
#define CP_COMMIT() asm volatile("cp.async.commit_group;" ::: "memory")
#define CP_WAIT(n)  asm volatile("cp.async.wait_group %0;" :: "n"(n) : "memory")

// ===========================================================================
// Kernel 1: weight synthesis + hi/lo split.  Block per ic.
// ===========================================================================
__global__ __launch_bounds__(256) void synth_kernel(
    const float* __restrict__ feature, const float* __restrict__ w0,
    const float* __restrict__ tb, const float* __restrict__ tq,
    const float* __restrict__ tn, const float* __restrict__ tx,
    const float* __restrict__ mb, const float* __restrict__ mq,
    const float* __restrict__ mn, const float* __restrict__ mx)
{
    __shared__ float sf[64];
    __shared__ float buf[2048];                   // [phase][tap][oc] for one (b, ic)

    const int ic = blockIdx.x;
    const int t  = threadIdx.x;
    if (t < 64) sf[t] = feature[t];
    __syncthreads();

    float base[8], ub[8], uq[8], un[8], ux[8];
    int   sidx[8];
    const int off = ic * 2048;

#pragma unroll
    for (int j = 0; j < 8; j++) {
        const int idx = t + 256 * j;              // = oc*16 + ky*4 + kx
        const int oc  = idx >> 4;
        const int kk  = idx & 15;
        const int ky  = kk >> 2, kx = kk & 3;
        const float mB = mb[ic * COUTC + oc], mQ = mq[ic * COUTC + oc];
        const float mN = mn[ic * COUTC + oc], mX = mx[ic * COUTC + oc];
        base[j] = w0[off + idx];
        ub[j] = tb[off + idx] * mB;
        uq[j] = tq[off + idx] * mQ;
        un[j] = tn[off + idx] * mN;
        ux[j] = tx[off + idx] * mX;
        const int py = 1 - (ky & 1), px = 1 - (kx & 1);
        const int tap = (ky >> 1) * 2 + (kx >> 1);
        sidx[j] = (py * 2 + px) * 512 + tap * 128 + oc;
    }

    for (int b = 0; b < BB; b++) {
        const float f0 = sf[b * 4 + 0], f1 = sf[b * 4 + 1];
        const float f2 = sf[b * 4 + 2], f3 = sf[b * 4 + 3];
#pragma unroll
        for (int j = 0; j < 8; j++)
            buf[sidx[j]] = base[j] + f0 * ub[j] + f1 * uq[j] + f2 * un[j] + f3 * ux[j];
        __syncthreads();
#pragma unroll
        for (int j = 0; j < 8; j++) {
            const int e = t + 256 * j;            // phase*512 + tap*128 + oc
            const float w = buf[e];
            const unsigned short hi = bf16_of(w);
            const float fh = __bfloat162float(__ushort_as_bfloat16(hi));
            const unsigned short lo = bf16_of(w - fh);
            const int plane2 = b * 16 + (e >> 7); // (b*4+phase)*4+tap
            g_wi[(size_t)(plane2 * 2 + 0) * 32768 + ic * 128 + (e & 127)] = hi;
            g_wi[(size_t)(plane2 * 2 + 1) * 32768 + ic * 128 + (e & 127)] = lo;
        }
        __syncthreads();
    }
}

// ===========================================================================
// Kernel 2: weight transpose [ic][oc] -> [oc][ic].  Grid (plane 512, icchunk 4)
// ===========================================================================
__global__ __launch_bounds__(256) void transposeW_kernel()
{
    __shared__ unsigned int sm[64][65];
    const int plane = blockIdx.x;
    const int ic0 = blockIdx.y * 64;
    const int t = threadIdx.x;
    const unsigned int* src = reinterpret_cast<const unsigned int*>(g_wi) + (size_t)plane * 16384;
    unsigned int*       dst = reinterpret_cast<unsigned int*>(g_wt) + (size_t)plane * 16384;

#pragma unroll
    for (int j = 0; j < 16; j++) {
        const int idx = t + 256 * j;          // 4096 u32
        const int icl = idx >> 6, oc2 = idx & 63;
        sm[icl][oc2] = src[(ic0 + icl) * 64 + oc2];
    }
    __syncthreads();
#pragma unroll
    for (int j = 0; j < 16; j++) {
        const int idx = t + 256 * j;
        const int oc = idx >> 5, icp = idx & 31;
        const unsigned int w0v = sm[icp * 2][oc >> 1];
        const unsigned int w1v = sm[icp * 2 + 1][oc >> 1];
        const int sh = (oc & 1) * 16;
        const unsigned int r = ((w0v >> sh) & 0xffffu) | (((w1v >> sh) & 0xffffu) << 16);
        dst[oc * 128 + (ic0 >> 1) + icp] = r;
    }
}

// ===========================================================================
// Kernel 3: zero only the halo border of g_xt (interior written by transposeX)
// per (b,prec)=bp: rows yy=0,65 (2112 float4 each) + cols xx=0,65 (4096 float4)
// ===========================================================================
#define BORDER_PER_BP 8320
__global__ __launch_bounds__(256) void zero_border_kernel()
{
    const int idx = blockIdx.x * 256 + threadIdx.x;
    if (idx >= 32 * BORDER_PER_BP) return;
    const int bp = idx / BORDER_PER_BP;
    const int r  = idx - bp * BORDER_PER_BP;
    float4* dst = reinterpret_cast<float4*>(g_xt) + (size_t)bp * 66 * 66 * 32;
    const float4 z = make_float4(0.f, 0.f, 0.f, 0.f);
    if (r < 4224) {
        const int yy  = (r < 2112) ? 0 : 65;
        const int off = (r < 2112) ? r : r - 2112;
        const int pix = off >> 5, c = off & 31;
        dst[((size_t)yy * 66 + pix) * 32 + c] = z;
    } else {
        const int j  = r - 4224;
        const int yy = 1 + (j >> 6);
        const int xx = ((j >> 5) & 1) ? 65 : 0;
        const int c  = j & 31;
        dst[((size_t)yy * 66 + xx) * 32 + c] = z;
    }
}

// ===========================================================================
// Kernel 4: x transpose + split: x[b][ic][y][x] -> g_xt[b][prec][y+1][x+1][ic]
// ===========================================================================
__global__ __launch_bounds__(256) void transposeX_kernel(const float* __restrict__ x)
{
    __shared__ float sm[128][65];
    const int bx = blockIdx.x;
    const int b = bx >> 6, y = bx & 63;
    const int t = threadIdx.x;

    for (int ic0 = 0; ic0 < 256; ic0 += 128) {
        __syncthreads();
#pragma unroll
        for (int j = 0; j < 32; j++) {
            const int idx = t + 256 * j;          // 8192
            const int icl = idx >> 6, xc = idx & 63;
            sm[icl][xc] = x[((size_t)(b * 256 + ic0 + icl) * 64 + y) * 64 + xc];
        }
        __syncthreads();
#pragma unroll
        for (int j = 0; j < 16; j++) {
            const int idx = t + 256 * j;          // 4096 u32
            const int xc = idx >> 6, icp = idx & 63;
            const float f0 = sm[icp * 2][xc], f1 = sm[icp * 2 + 1][xc];
            const unsigned short h0 = bf16_of(f0), h1 = bf16_of(f1);
            const float fh0 = __bfloat162float(__ushort_as_bfloat16(h0));
            const float fh1 = __bfloat162float(__ushort_as_bfloat16(h1));
            const unsigned short l0 = bf16_of(f0 - fh0), l1 = bf16_of(f1 - fh1);
            const unsigned int hw = (unsigned int)h0 | ((unsigned int)h1 << 16);
            const unsigned int lw = (unsigned int)l0 | ((unsigned int)l1 << 16);
            const size_t rh = (((size_t)(b * 2 + 0) * 66 + (y + 1)) * 66 + (xc + 1));
            const size_t rl = (((size_t)(b * 2 + 1) * 66 + (y + 1)) * 66 + (xc + 1));
            unsigned int* xt32 = reinterpret_cast<unsigned int*>(g_xt);
            xt32[rh * 128 + (ic0 >> 1) + icp] = hw;
            xt32[rl * 128 + (ic0 >> 1) + icp] = lw;
        }
    }
}

// ===========================================================================
// Kernel 5: mma.sync bf16 GEMM, cp.async double-buffered, 64B swizzled rows.
// Grid (ytile 16, phase 4, b 16), 256 thr.  CTA tile 128 oc x 256 px.
// Per buffer: sx [prec2][325 rows][64B] = 41600 ; sA [8 tiles][128][64B] = 65536
// ===========================================================================
#define SXP        20800                          // 325*64
#define SA_OFF     41600                          // = 325*128, 128B aligned
#define BUF_STRIDE 107520                         // 41600+65536 padded to 1KB
#define SMEM_BYTES (2 * BUF_STRIDE)               // 215040

__global__ __launch_bounds__(256)
void gemm_kernel(const float* __restrict__ bias,
                 const float* __restrict__ prelu_a,
                 float* __restrict__ out)
{
    extern __shared__ char smem[];
    const uint32_t s0 = smem_u32(smem);

    const int t = threadIdx.x, wid = t >> 5, lane = t & 31;
    const int ytile = blockIdx.x, phase = blockIdx.y, b = blockIdx.z;
    const int py = phase >> 1, px = phase & 1;
    const int y0 = ytile * 4;
    const int dymin = (py == 0) ? -1 : 0;
    const int dxmin = (px == 0) ? -1 : 0;

    const int warp_m = wid & 1;                   // m_base = warp_m*64
    const int warp_n = wid >> 1;                  // output row within tile (0..3)
    const int m_base = warp_m * 64;

    // ldmatrix per-lane addressing
    const int a_row  = lane & 15;
    const int a_coff = lane >> 4;                 // 0/1 -> 16B half within k16
    const int a_sw   = (a_row >> 1) & 3;
    const int b_row  = ((lane >> 4) & 1) * 8 + (lane & 7);
    const int b_coff = (lane >> 3) & 1;

    float acc[4][8][4];
#pragma unroll
    for (int ma = 0; ma < 4; ma++)
#pragma unroll
        for (int j = 0; j < 8; j++)
#pragma unroll
            for (int q = 0; q < 4; q++) acc[ma][j][q] = 0.f;

    const char* gxt = reinterpret_cast<const char*>(g_xt);
    const char* gwt = reinterpret_cast<const char*>(g_wt);

    // ---- staging via cp.async (16B) into swizzled 64B rows -----------------
    auto stage = [&](int ic0, int buf) {
        const uint32_t sb = s0 + buf * BUF_STRIDE;
        for (int i = t; i < 2600; i += 256) {
            const int prec = (i >= 1300) ? 1 : 0;
            const int j = i - prec * 1300;
            const int p = j >> 2, c = j & 3;
            const int jj = p / 65, xi = p - jj * 65;
            const int yy = y0 + dymin + jj + 1;    // in [0,65]
            const int xx = dxmin + xi + 1;         // in [0,65]
            const char* src = gxt
                + (((size_t)(b * 2 + prec) * 66 + yy) * 66 + xx) * 512
                + ic0 * 2 + c * 16;
            cp16(sb + prec * SXP + p * 64 + ((c ^ ((p >> 1) & 3)) << 4), src);
        }
        for (int i = t; i < 4096; i += 256) {
            const int c = i & 3, oc = (i >> 2) & 127, tile = i >> 9;
            const int tap = tile >> 1, aprec = tile & 1;
            const int plane = ((b * 4 + phase) * 4 + tap) * 2 + aprec;
            const char* src = gwt + (size_t)plane * 65536 + oc * 512
                + ic0 * 2 + c * 16;
            cp16(sb + SA_OFF + tile * 8192 + oc * 64
                 + ((c ^ ((oc >> 1) & 3)) << 4), src);
        }
    };

    stage(0, 0);
    CP_COMMIT();

    for (int chunk = 0; chunk < 8; chunk++) {
        __syncthreads();                          // prior compute done -> safe overwrite
        if (chunk < 7) {
            stage((chunk + 1) * 32, (chunk + 1) & 1);
            CP_COMMIT();
            CP_WAIT(1);                           // chunk's own stage complete
        } else {
            CP_WAIT(0);
        }
        __syncthreads();                          // staged data visible to all

        const uint32_t sb   = s0 + (chunk & 1) * BUF_STRIDE;
        const uint32_t sa_u = sb + SA_OFF;

#pragma unroll
        for (int kk = 0; kk < 2; kk++) {
#pragma unroll
            for (int tap = 0; tap < 4; tap++) {
                const int tky = tap >> 1, tkx = tap & 1;
                const int pbase = (warp_n + 1 - tky) * 65 + (1 - tkx);
                const int brow0 = pbase + b_row;
                const uint32_t boff = brow0 * 64
                    + (((kk * 2 + b_coff) ^ ((brow0 >> 1) & 3)) << 4);
                const uint32_t aoff = (m_base + a_row) * 64
                    + (((kk * 2 + a_coff) ^ a_sw) << 4);

                uint32_t ah[4][4], bh[4][4];
#pragma unroll
                for (int ma = 0; ma < 4; ma++)
                    ldm_x4(ah[ma], sa_u + (tap * 2 + 0) * 8192 + aoff + ma * 1024);
#pragma unroll
                for (int nb = 0; nb < 4; nb++)
                    ldm_x4(bh[nb], sb + 0 * SXP + boff + nb * 1024);
#pragma unroll
                for (int ma = 0; ma < 4; ma++)
#pragma unroll
                    for (int j = 0; j < 8; j++)
                        mma_bf16(acc[ma][j], ah[ma], bh[j >> 1][(j & 1) * 2],
                                 bh[j >> 1][(j & 1) * 2 + 1]);

                // lo(A) x hi(B)
                {
                    uint32_t al[4][4];
#pragma unroll
                    for (int ma = 0; ma < 4; ma++)
                        ldm_x4(al[ma], sa_u + (tap * 2 + 1) * 8192 + aoff + ma * 1024);
#pragma unroll
                    for (int ma = 0; ma < 4; ma++)
#pragma unroll
                        for (int j = 0; j < 8; j++)
                            mma_bf16(acc[ma][j], al[ma], bh[j >> 1][(j & 1) * 2],
                                     bh[j >> 1][(j & 1) * 2 + 1]);
                }
                // hi(A) x lo(B)
                {
                    uint32_t bl[4][4];
#pragma unroll
                    for (int nb = 0; nb < 4; nb++)
                        ldm_x4(bl[nb], sb + 1 * SXP + boff + nb * 1024);
#pragma unroll
                    for (int ma = 0; ma < 4; ma++)
#pragma unroll
                        for (int j = 0; j < 8; j++)
                            mma_bf16(acc[ma][j], ah[ma], bl[j >> 1][(j & 1) * 2],
                                     bl[j >> 1][(j & 1) * 2 + 1]);
                }
            }
        }
    }

    // ---- epilogue: bias + PReLU, scattered stride-2 stores
    const float pa = prelu_a[0];
    const int oy = 2 * (y0 + warp_n) + py;
#pragma unroll
    for (int ma = 0; ma < 4; ma++) {
        const int m0 = m_base + ma * 16 + (lane >> 2);
        const float bz0 = bias[m0];
        const float bz1 = bias[m0 + 8];
        float* r0 = out + ((size_t)(b * COUTC + m0) * OH + oy) * OW + px;
        float* r1 = out + ((size_t)(b * COUTC + m0 + 8) * OH + oy) * OW + px;
#pragma unroll
        for (int j = 0; j < 8; j++) {
            const int col = j * 8 + (lane & 3) * 2;
            float v0 = acc[ma][j][0] + bz0;
            float v1 = acc[ma][j][1] + bz0;
            float v2 = acc[ma][j][2] + bz1;
            float v3 = acc[ma][j][3] + bz1;
            v0 = (v0 >= 0.f) ? v0 : pa * v0;
            v1 = (v1 >= 0.f) ? v1 : pa * v1;
            v2 = (v2 >= 0.f) ? v2 : pa * v2;
            v3 = (v3 >= 0.f) ? v3 : pa * v3;
            r0[2 * col]       = v0;
            r0[2 * (col + 1)] = v1;
            r1[2 * col]       = v2;
            r1[2 * (col + 1)] = v3;
        }
    }
}

// ===========================================================================
extern "C" void kernel_launch(void* const* d_in, const int* in_sizes, int n_in,
                              void* d_out, int out_size)
{
    const float* x       = (const float*)d_in[0];
    const float* feature = (const float*)d_in[1];
    const float* weight  = (const float*)d_in[2];
    const float* tb      = (const float*)d_in[3];
    const float* tq      = (const float*)d_in[4];
    const float* tn      = (const float*)d_in[5];
    const float* tx      = (const float*)d_in[6];
    const float* mb      = (const float*)d_in[7];
    const float* mq      = (const float*)d_in[8];
    const float* mn      = (const float*)d_in[9];
    const float* mx      = (const float*)d_in[10];
    const float* bias    = (const float*)d_in[11];
    const float* prelu_a = (const float*)d_in[12];
    float* out = (float*)d_out;

    cudaFuncSetAttribute(gemm_kernel,
                         cudaFuncAttributeMaxDynamicSharedMemorySize, SMEM_BYTES);

    zero_border_kernel<<<(32 * BORDER_PER_BP + 255) / 256, 256>>>();
    transposeX_kernel<<<1024, 256>>>(x);
    synth_kernel<<<256, 256>>>(feature, weight, tb, tq, tn, tx, mb, mq, mn, mx);
    dim3 gw(512, 4);
    transposeW_kernel<<<gw, 256>>>();

    dim3 grid(16, 4, 16);
    gemm_kernel<<<grid, 256, SMEM_BYTES>>>(bias, prelu_a, out);
}

// round 7
// speedup vs baseline: 4.8994x; 1.3020x over previous
#include <cuda_runtime.h>
#include <cuda_fp16.h>
#include <cstdint>

#define BB   16
#define CINC 256
#define COUTC 128
#define HH   64
#define WW   64
#define OH   128
#define OW   128

// ===========================================================================
// Device scratch (static allocation — allowed)
// g_wi: synthesized fp16 weights, [plane = (b*4+ph)*4+tap][ic 256][oc 128] fp16
// g_wt: transposed,               [plane][oc 128][ic 256] fp16
// g_xt: transposed input hi/lo,   [b][prec][yy 66][xx 66][ic 256] fp16
// ===========================================================================
__device__ __align__(16) unsigned short g_wi[256u * 256 * 128];
__device__ __align__(16) unsigned short g_wt[256u * 256 * 128];
__device__ __align__(16) unsigned short g_xt[16u * 2 * 66 * 66 * 256];

__device__ __forceinline__ unsigned short h16_of(float f) {
    return __half_as_ushort(__float2half_rn(f));
}
__device__ __forceinline__ uint32_t smem_u32(const void* p) {
    uint32_t a;
    asm("{ .reg .u64 tmp; cvta.to.shared.u64 tmp, %1; cvt.u32.u64 %0, tmp; }"
        : "=r"(a) : "l"(p));
    return a;
}
__device__ __forceinline__ void ldm_x4(uint32_t* r, uint32_t addr) {
    asm volatile("ldmatrix.sync.aligned.m8n8.x4.shared.b16 {%0,%1,%2,%3}, [%4];"
                 : "=r"(r[0]), "=r"(r[1]), "=r"(r[2]), "=r"(r[3]) : "r"(addr));
}
__device__ __forceinline__ void mma_fp16(float* c, const uint32_t* a,
                                         uint32_t b0, uint32_t b1) {
    asm volatile("mma.sync.aligned.m16n8k16.row.col.f32.f16.f16.f32 "
                 "{%0,%1,%2,%3}, {%4,%5,%6,%7}, {%8,%9}, {%0,%1,%2,%3};"
                 : "+f"(c[0]), "+f"(c[1]), "+f"(c[2]), "+f"(c[3])
                 : "r"(a[0]), "r"(a[1]), "r"(a[2]), "r"(a[3]), "r"(b0), "r"(b1));
}
__device__ __forceinline__ void cp16(uint32_t saddr, const void* g) {
    asm volatile("cp.async.cg.shared.global [%0], [%1], 16;"
                 :: "r"(saddr), "l"(g) : "memory");
}
#define CP_COMMIT() asm volatile("cp.async.commit_group;" ::: "memory")
#define CP_WAIT(n)  asm volatile("cp.async.wait_group %0;" :: "n"(n) : "memory")

// ===========================================================================
// Kernel 1: weight synthesis (single fp16).  Block per ic.
// ===========================================================================
__global__ __launch_bounds__(256) void synth_kernel(
    const float* __restrict__ feature, const float* __restrict__ w0,
    const float* __restrict__ tb, const float* __restrict__ tq,
    const float* __restrict__ tn, const float* __restrict__ tx,
    const float* __restrict__ mb, const float* __restrict__ mq,
    const float* __restrict__ mn, const float* __restrict__ mx)
{
    __shared__ float sf[64];
    __shared__ float buf[2048];                   // [phase][tap][oc] for one (b, ic)

    const int ic = blockIdx.x;
    const int t  = threadIdx.x;
    if (t < 64) sf[t] = feature[t];
    __syncthreads();

    float base[8], ub[8], uq[8], un[8], ux[8];
    int   sidx[8];
    const int off = ic * 2048;

#pragma unroll
    for (int j = 0; j < 8; j++) {
        const int idx = t + 256 * j;              // = oc*16 + ky*4 + kx
        const int oc  = idx >> 4;
        const int kk  = idx & 15;
        const int ky  = kk >> 2, kx = kk & 3;
        const float mB = mb[ic * COUTC + oc], mQ = mq[ic * COUTC + oc];
        const float mN = mn[ic * COUTC + oc], mX = mx[ic * COUTC + oc];
        base[j] = w0[off + idx];
        ub[j] = tb[off + idx] * mB;
        uq[j] = tq[off + idx] * mQ;
        un[j] = tn[off + idx] * mN;
        ux[j] = tx[off + idx] * mX;
        const int py = 1 - (ky & 1), px = 1 - (kx & 1);
        const int tap = (ky >> 1) * 2 + (kx >> 1);
        sidx[j] = (py * 2 + px) * 512 + tap * 128 + oc;
    }

    for (int b = 0; b < BB; b++) {
        const float f0 = sf[b * 4 + 0], f1 = sf[b * 4 + 1];
        const float f2 = sf[b * 4 + 2], f3 = sf[b * 4 + 3];
#pragma unroll
        for (int j = 0; j < 8; j++)
            buf[sidx[j]] = base[j] + f0 * ub[j] + f1 * uq[j] + f2 * un[j] + f3 * ux[j];
        __syncthreads();
#pragma unroll
        for (int j = 0; j < 8; j++) {
            const int e = t + 256 * j;            // phase*512 + tap*128 + oc
            const int plane = b * 16 + (e >> 7);  // (b*4+phase)*4+tap
            g_wi[(size_t)plane * 32768 + ic * 128 + (e & 127)] = h16_of(buf[e]);
        }
        __syncthreads();
    }
}

// ===========================================================================
// Kernel 2: weight transpose [ic][oc] -> [oc][ic].  Grid (plane 256, icchunk 4)
// ===========================================================================
__global__ __launch_bounds__(256) void transposeW_kernel()
{
    __shared__ unsigned int sm[64][65];
    const int plane = blockIdx.x;
    const int ic0 = blockIdx.y * 64;
    const int t = threadIdx.x;
    const unsigned int* src = reinterpret_cast<const unsigned int*>(g_wi) + (size_t)plane * 16384;
    unsigned int*       dst = reinterpret_cast<unsigned int*>(g_wt) + (size_t)plane * 16384;

#pragma unroll
    for (int j = 0; j < 16; j++) {
        const int idx = t + 256 * j;          // 4096 u32
        const int icl = idx >> 6, oc2 = idx & 63;
        sm[icl][oc2] = src[(ic0 + icl) * 64 + oc2];
    }
    __syncthreads();
#pragma unroll
    for (int j = 0; j < 16; j++) {
        const int idx = t + 256 * j;
        const int oc = idx >> 5, icp = idx & 31;
        const unsigned int w0v = sm[icp * 2][oc >> 1];
        const unsigned int w1v = sm[icp * 2 + 1][oc >> 1];
        const int sh = (oc & 1) * 16;
        const unsigned int r = ((w0v >> sh) & 0xffffu) | (((w1v >> sh) & 0xffffu) << 16);
        dst[oc * 128 + (ic0 >> 1) + icp] = r;
    }
}

// ===========================================================================
// Kernel 3: zero only the halo border of g_xt (interior written by transposeX)
// per (b,prec)=bp: rows yy=0,65 (2112 float4 each) + cols xx=0,65 (4096 float4)
// ===========================================================================
#define BORDER_PER_BP 8320
__global__ __launch_bounds__(256) void zero_border_kernel()
{
    const int idx = blockIdx.x * 256 + threadIdx.x;
    if (idx >= 32 * BORDER_PER_BP) return;
    const int bp = idx / BORDER_PER_BP;
    const int r  = idx - bp * BORDER_PER_BP;
    float4* dst = reinterpret_cast<float4*>(g_xt) + (size_t)bp * 66 * 66 * 32;
    const float4 z = make_float4(0.f, 0.f, 0.f, 0.f);
    if (r < 4224) {
        const int yy  = (r < 2112) ? 0 : 65;
        const int off = (r < 2112) ? r : r - 2112;
        const int pix = off >> 5, c = off & 31;
        dst[((size_t)yy * 66 + pix) * 32 + c] = z;
    } else {
        const int j  = r - 4224;
        const int yy = 1 + (j >> 6);
        const int xx = ((j >> 5) & 1) ? 65 : 0;
        const int c  = j & 31;
        dst[((size_t)yy * 66 + xx) * 32 + c] = z;
    }
}

// ===========================================================================
// Kernel 4: x transpose + fp16 hi/lo split:
// x[b][ic][y][x] -> g_xt[b][prec][y+1][x+1][ic]
// ===========================================================================
__global__ __launch_bounds__(256) void transposeX_kernel(const float* __restrict__ x)
{
    __shared__ float sm[128][65];
    const int bx = blockIdx.x;
    const int b = bx >> 6, y = bx & 63;
    const int t = threadIdx.x;

    for (int ic0 = 0; ic0 < 256; ic0 += 128) {
        __syncthreads();
#pragma unroll
        for (int j = 0; j < 32; j++) {
            const int idx = t + 256 * j;          // 8192
            const int icl = idx >> 6, xc = idx & 63;
            sm[icl][xc] = x[((size_t)(b * 256 + ic0 + icl) * 64 + y) * 64 + xc];
        }
        __syncthreads();
#pragma unroll
        for (int j = 0; j < 16; j++) {
            const int idx = t + 256 * j;          // 4096 u32
            const int xc = idx >> 6, icp = idx & 63;
            const float f0 = sm[icp * 2][xc], f1 = sm[icp * 2 + 1][xc];
            const unsigned short h0 = h16_of(f0), h1 = h16_of(f1);
            const float fh0 = __half2float(__ushort_as_half(h0));
            const float fh1 = __half2float(__ushort_as_half(h1));
            const unsigned short l0 = h16_of(f0 - fh0), l1 = h16_of(f1 - fh1);
            const unsigned int hw = (unsigned int)h0 | ((unsigned int)h1 << 16);
            const unsigned int lw = (unsigned int)l0 | ((unsigned int)l1 << 16);
            const size_t rh = (((size_t)(b * 2 + 0) * 66 + (y + 1)) * 66 + (xc + 1));
            const size_t rl = (((size_t)(b * 2 + 1) * 66 + (y + 1)) * 66 + (xc + 1));
            unsigned int* xt32 = reinterpret_cast<unsigned int*>(g_xt);
            xt32[rh * 128 + (ic0 >> 1) + icp] = hw;
            xt32[rl * 128 + (ic0 >> 1) + icp] = lw;
        }
    }
}

// ===========================================================================
// Kernel 5: mma.sync fp16 GEMM (2-pass: w * x_hi + w * x_lo),
// cp.async double-buffered, 64B swizzled rows.
// Grid (ytile 16, phase 4, b 16), 256 thr.  CTA tile 128 oc x 256 px.
// Per buffer: sx [prec2][325 rows][64B] = 41600 ; sA [4 taps][128][64B] = 32768
// ===========================================================================
#define SXP        20800                          // 325*64
#define SA_OFF     41600                          // 2*SXP, 128B aligned
#define BUF_STRIDE 74752                          // 41600+32768 padded to 1KB
#define SMEM_BYTES (2 * BUF_STRIDE)               // 149504

__global__ __launch_bounds__(256)
void gemm_kernel(const float* __restrict__ bias,
                 const float* __restrict__ prelu_a,
                 float* __restrict__ out)
{
    extern __shared__ char smem[];
    const uint32_t s0 = smem_u32(smem);

    const int t = threadIdx.x, wid = t >> 5, lane = t & 31;
    const int ytile = blockIdx.x, phase = blockIdx.y, b = blockIdx.z;
    const int py = phase >> 1, px = phase & 1;
    const int y0 = ytile * 4;
    const int dymin = (py == 0) ? -1 : 0;
    const int dxmin = (px == 0) ? -1 : 0;

    const int warp_m = wid & 1;                   // m_base = warp_m*64
    const int warp_n = wid >> 1;                  // output row within tile (0..3)
    const int m_base = warp_m * 64;

    // ldmatrix per-lane addressing
    const int a_row  = lane & 15;
    const int a_coff = lane >> 4;                 // 0/1 -> 16B half within k16
    const int a_sw   = (a_row >> 1) & 3;
    const int b_row  = ((lane >> 4) & 1) * 8 + (lane & 7);
    const int b_coff = (lane >> 3) & 1;

    float acc[4][8][4];
#pragma unroll
    for (int ma = 0; ma < 4; ma++)
#pragma unroll
        for (int j = 0; j < 8; j++)
#pragma unroll
            for (int q = 0; q < 4; q++) acc[ma][j][q] = 0.f;

    const char* gxt = reinterpret_cast<const char*>(g_xt);
    const char* gwt = reinterpret_cast<const char*>(g_wt);

    // ---- staging via cp.async (16B) into swizzled 64B rows -----------------
    auto stage = [&](int ic0, int buf) {
        const uint32_t sb = s0 + buf * BUF_STRIDE;
        for (int i = t; i < 2600; i += 256) {
            const int prec = (i >= 1300) ? 1 : 0;
            const int j = i - prec * 1300;
            const int p = j >> 2, c = j & 3;
            const int jj = p / 65, xi = p - jj * 65;
            const int yy = y0 + dymin + jj + 1;    // in [0,65]
            const int xx = dxmin + xi + 1;         // in [0,65]
            const char* src = gxt
                + (((size_t)(b * 2 + prec) * 66 + yy) * 66 + xx) * 512
                + ic0 * 2 + c * 16;
            cp16(sb + prec * SXP + p * 64 + ((c ^ ((p >> 1) & 3)) << 4), src);
        }
        for (int i = t; i < 2048; i += 256) {
            const int c = i & 3, oc = (i >> 2) & 127, tap = i >> 9;
            const int plane = (b * 4 + phase) * 4 + tap;
            const char* src = gwt + (size_t)plane * 65536 + oc * 512
                + ic0 * 2 + c * 16;
            cp16(sb + SA_OFF + tap * 8192 + oc * 64
                 + ((c ^ ((oc >> 1) & 3)) << 4), src);
        }
    };

    stage(0, 0);
    CP_COMMIT();

    for (int chunk = 0; chunk < 8; chunk++) {
        __syncthreads();                          // prior compute done -> safe overwrite
        if (chunk < 7) {
            stage((chunk + 1) * 32, (chunk + 1) & 1);
            CP_COMMIT();
            CP_WAIT(1);                           // chunk's own stage complete
        } else {
            CP_WAIT(0);
        }
        __syncthreads();                          // staged data visible to all

        const uint32_t sb   = s0 + (chunk & 1) * BUF_STRIDE;
        const uint32_t sa_u = sb + SA_OFF;

#pragma unroll
        for (int kk = 0; kk < 2; kk++) {
#pragma unroll
            for (int tap = 0; tap < 4; tap++) {
                const int tky = tap >> 1, tkx = tap & 1;
                const int pbase = (warp_n + 1 - tky) * 65 + (1 - tkx);
                const int brow0 = pbase + b_row;
                const uint32_t boff = brow0 * 64
                    + (((kk * 2 + b_coff) ^ ((brow0 >> 1) & 3)) << 4);
                const uint32_t aoff = (m_base + a_row) * 64
                    + (((kk * 2 + a_coff) ^ a_sw) << 4);

                uint32_t ah[4][4], bh[4][4];
#pragma unroll
                for (int ma = 0; ma < 4; ma++)
                    ldm_x4(ah[ma], sa_u + tap * 8192 + aoff + ma * 1024);
#pragma unroll
                for (int nb = 0; nb < 4; nb++)
                    ldm_x4(bh[nb], sb + 0 * SXP + boff + nb * 1024);
#pragma unroll
                for (int ma = 0; ma < 4; ma++)
#pragma unroll
                    for (int j = 0; j < 8; j++)
                        mma_fp16(acc[ma][j], ah[ma], bh[j >> 1][(j & 1) * 2],
                                 bh[j >> 1][(j & 1) * 2 + 1]);

                // w * x_lo
                {
                    uint32_t bl[4][4];
#pragma unroll
                    for (int nb = 0; nb < 4; nb++)
                        ldm_x4(bl[nb], sb + 1 * SXP + boff + nb * 1024);
#pragma unroll
                    for (int ma = 0; ma < 4; ma++)
#pragma unroll
                        for (int j = 0; j < 8; j++)
                            mma_fp16(acc[ma][j], ah[ma], bl[j >> 1][(j & 1) * 2],
                                     bl[j >> 1][(j & 1) * 2 + 1]);
                }
            }
        }
    }

    // ---- epilogue: bias + PReLU, scattered stride-2 stores
    const float pa = prelu_a[0];
    const int oy = 2 * (y0 + warp_n) + py;
#pragma unroll
    for (int ma = 0; ma < 4; ma++) {
        const int m0 = m_base + ma * 16 + (lane >> 2);
        const float bz0 = bias[m0];
        const float bz1 = bias[m0 + 8];
        float* r0 = out + ((size_t)(b * COUTC + m0) * OH + oy) * OW + px;
        float* r1 = out + ((size_t)(b * COUTC + m0 + 8) * OH + oy) * OW + px;
#pragma unroll
        for (int j = 0; j < 8; j++) {
            const int col = j * 8 + (lane & 3) * 2;
            float v0 = acc[ma][j][0] + bz0;
            float v1 = acc[ma][j][1] + bz0;
            float v2 = acc[ma][j][2] + bz1;
            float v3 = acc[ma][j][3] + bz1;
            v0 = (v0 >= 0.f) ? v0 : pa * v0;
            v1 = (v1 >= 0.f) ? v1 : pa * v1;
            v2 = (v2 >= 0.f) ? v2 : pa * v2;
            v3 = (v3 >= 0.f) ? v3 : pa * v3;
            r0[2 * col]       = v0;
            r0[2 * (col + 1)] = v1;
            r1[2 * col]       = v2;
            r1[2 * (col + 1)] = v3;
        }
    }
}

// ===========================================================================
extern "C" void kernel_launch(void* const* d_in, const int* in_sizes, int n_in,
                              void* d_out, int out_size)
{
    const float* x       = (const float*)d_in[0];
    const float* feature = (const float*)d_in[1];
    const float* weight  = (const float*)d_in[2];
    const float* tb      = (const float*)d_in[3];
    const float* tq      = (const float*)d_in[4];
    const float* tn      = (const float*)d_in[5];
    const float* tx      = (const float*)d_in[6];
    const float* mb      = (const float*)d_in[7];
    const float* mq      = (const float*)d_in[8];
    const float* mn      = (const float*)d_in[9];
    const float* mx      = (const float*)d_in[10];
    const float* bias    = (const float*)d_in[11];
    const float* prelu_a = (const float*)d_in[12];
    float* out = (float*)d_out;

    cudaFuncSetAttribute(gemm_kernel,
                         cudaFuncAttributeMaxDynamicSharedMemorySize, SMEM_BYTES);

    zero_border_kernel<<<(32 * BORDER_PER_BP + 255) / 256, 256>>>();
    transposeX_kernel<<<1024, 256>>>(x);
    synth_kernel<<<256, 256>>>(feature, weight, tb, tq, tn, tx, mb, mq, mn, mx);
    dim3 gw(256, 4);
    transposeW_kernel<<<gw, 256>>>();

    dim3 grid(16, 4, 16);
    gemm_kernel<<<grid, 256, SMEM_BYTES>>>(bias, prelu_a, out);
}

// round 8
// speedup vs baseline: 6.6312x; 1.3535x over previous
#include <cuda_runtime.h>
#include <cuda_fp16.h>
#include <cstdint>

#define BB   16
#define CINC 256
#define COUTC 128
#define HH   64
#define WW   64
#define OH   128
#define OW   128

// ===========================================================================
// Device scratch (static allocation — allowed)
// g_wi: synthesized fp16 weights, [plane = (b*4+ph)*4+tap][ic 256][oc 128] fp16
// g_wt: transposed,               [plane][oc 128][ic 256] fp16
// g_xt: transposed input,         [b][yy 66][xx 66][ic 256] fp16
// ===========================================================================
__device__ __align__(16) unsigned short g_wi[256u * 256 * 128];
__device__ __align__(16) unsigned short g_wt[256u * 256 * 128];
__device__ __align__(16) unsigned short g_xt[16u * 66 * 66 * 256];

__device__ __forceinline__ unsigned short h16_of(float f) {
    return __half_as_ushort(__float2half_rn(f));
}
__device__ __forceinline__ uint32_t smem_u32(const void* p) {
    uint32_t a;
    asm("{ .reg .u64 tmp; cvta.to.shared.u64 tmp, %1; cvt.u32.u64 %0, tmp; }"
        : "=r"(a) : "l"(p));
    return a;
}
__device__ __forceinline__ void ldm_x4(uint32_t* r, uint32_t addr) {
    asm volatile("ldmatrix.sync.aligned.m8n8.x4.shared.b16 {%0,%1,%2,%3}, [%4];"
                 : "=r"(r[0]), "=r"(r[1]), "=r"(r[2]), "=r"(r[3]) : "r"(addr));
}
__device__ __forceinline__ void mma_fp16(float* c, const uint32_t* a,
                                         uint32_t b0, uint32_t b1) {
    asm volatile("mma.sync.aligned.m16n8k16.row.col.f32.f16.f16.f32 "
                 "{%0,%1,%2,%3}, {%4,%5,%6,%7}, {%8,%9}, {%0,%1,%2,%3};"
                 : "+f"(c[0]), "+f"(c[1]), "+f"(c[2]), "+f"(c[3])
                 : "r"(a[0]), "r"(a[1]), "r"(a[2]), "r"(a[3]), "r"(b0), "r"(b1));
}
__device__ __forceinline__ void cp16(uint32_t saddr, const void* g) {
    asm volatile("cp.async.cg.shared.global [%0], [%1], 16;"
                 :: "r"(saddr), "l"(g) : "memory");
}
#define CP_COMMIT() asm volatile("cp.async.commit_group;" ::: "memory")
#define CP_WAIT(n)  asm volatile("cp.async.wait_group %0;" :: "n"(n) : "memory")

// ===========================================================================
// Kernel 1: weight synthesis (single fp16).  Block per ic.
// ===========================================================================
__global__ __launch_bounds__(256) void synth_kernel(
    const float* __restrict__ feature, const float* __restrict__ w0,
    const float* __restrict__ tb, const float* __restrict__ tq,
    const float* __restrict__ tn, const float* __restrict__ tx,
    const float* __restrict__ mb, const float* __restrict__ mq,
    const float* __restrict__ mn, const float* __restrict__ mx)
{
    __shared__ float sf[64];
    __shared__ float buf[2048];                   // [phase][tap][oc] for one (b, ic)

    const int ic = blockIdx.x;
    const int t  = threadIdx.x;
    if (t < 64) sf[t] = feature[t];
    __syncthreads();

    float base[8], ub[8], uq[8], un[8], ux[8];
    int   sidx[8];
    const int off = ic * 2048;

#pragma unroll
    for (int j = 0; j < 8; j++) {
        const int idx = t + 256 * j;              // = oc*16 + ky*4 + kx
        const int oc  = idx >> 4;
        const int kk  = idx & 15;
        const int ky  = kk >> 2, kx = kk & 3;
        const float mB = mb[ic * COUTC + oc], mQ = mq[ic * COUTC + oc];
        const float mN = mn[ic * COUTC + oc], mX = mx[ic * COUTC + oc];
        base[j] = w0[off + idx];
        ub[j] = tb[off + idx] * mB;
        uq[j] = tq[off + idx] * mQ;
        un[j] = tn[off + idx] * mN;
        ux[j] = tx[off + idx] * mX;
        const int py = 1 - (ky & 1), px = 1 - (kx & 1);
        const int tap = (ky >> 1) * 2 + (kx >> 1);
        sidx[j] = (py * 2 + px) * 512 + tap * 128 + oc;
    }

    for (int b = 0; b < BB; b++) {
        const float f0 = sf[b * 4 + 0], f1 = sf[b * 4 + 1];
        const float f2 = sf[b * 4 + 2], f3 = sf[b * 4 + 3];
#pragma unroll
        for (int j = 0; j < 8; j++)
            buf[sidx[j]] = base[j] + f0 * ub[j] + f1 * uq[j] + f2 * un[j] + f3 * ux[j];
        __syncthreads();
#pragma unroll
        for (int j = 0; j < 8; j++) {
            const int e = t + 256 * j;            // phase*512 + tap*128 + oc
            const int plane = b * 16 + (e >> 7);  // (b*4+phase)*4+tap
            g_wi[(size_t)plane * 32768 + ic * 128 + (e & 127)] = h16_of(buf[e]);
        }
        __syncthreads();
    }
}

// ===========================================================================
// Kernel 2: weight transpose [ic][oc] -> [oc][ic].  Grid (plane 256, icchunk 4)
// ===========================================================================
__global__ __launch_bounds__(256) void transposeW_kernel()
{
    __shared__ unsigned int sm[64][65];
    const int plane = blockIdx.x;
    const int ic0 = blockIdx.y * 64;
    const int t = threadIdx.x;
    const unsigned int* src = reinterpret_cast<const unsigned int*>(g_wi) + (size_t)plane * 16384;
    unsigned int*       dst = reinterpret_cast<unsigned int*>(g_wt) + (size_t)plane * 16384;

#pragma unroll
    for (int j = 0; j < 16; j++) {
        const int idx = t + 256 * j;          // 4096 u32
        const int icl = idx >> 6, oc2 = idx & 63;
        sm[icl][oc2] = src[(ic0 + icl) * 64 + oc2];
    }
    __syncthreads();
#pragma unroll
    for (int j = 0; j < 16; j++) {
        const int idx = t + 256 * j;
        const int oc = idx >> 5, icp = idx & 31;
        const unsigned int w0v = sm[icp * 2][oc >> 1];
        const unsigned int w1v = sm[icp * 2 + 1][oc >> 1];
        const int sh = (oc & 1) * 16;
        const unsigned int r = ((w0v >> sh) & 0xffffu) | (((w1v >> sh) & 0xffffu) << 16);
        dst[oc * 128 + (ic0 >> 1) + icp] = r;
    }
}

// ===========================================================================
// Kernel 3: zero only the halo border of g_xt (interior written by transposeX)
// per b: rows yy=0,65 (2112 float4 each) + cols xx=0,65 (4096 float4)
// ===========================================================================
#define BORDER_PER_BP 8320
__global__ __launch_bounds__(256) void zero_border_kernel()
{
    const int idx = blockIdx.x * 256 + threadIdx.x;
    if (idx >= 16 * BORDER_PER_BP) return;
    const int bp = idx / BORDER_PER_BP;
    const int r  = idx - bp * BORDER_PER_BP;
    float4* dst = reinterpret_cast<float4*>(g_xt) + (size_t)bp * 66 * 66 * 32;
    const float4 z = make_float4(0.f, 0.f, 0.f, 0.f);
    if (r < 4224) {
        const int yy  = (r < 2112) ? 0 : 65;
        const int off = (r < 2112) ? r : r - 2112;
        const int pix = off >> 5, c = off & 31;
        dst[((size_t)yy * 66 + pix) * 32 + c] = z;
    } else {
        const int j  = r - 4224;
        const int yy = 1 + (j >> 6);
        const int xx = ((j >> 5) & 1) ? 65 : 0;
        const int c  = j & 31;
        dst[((size_t)yy * 66 + xx) * 32 + c] = z;
    }
}

// ===========================================================================
// Kernel 4: x transpose to fp16: x[b][ic][y][x] -> g_xt[b][y+1][x+1][ic]
// ===========================================================================
__global__ __launch_bounds__(256) void transposeX_kernel(const float* __restrict__ x)
{
    __shared__ float sm[128][65];
    const int bx = blockIdx.x;
    const int b = bx >> 6, y = bx & 63;
    const int t = threadIdx.x;

    for (int ic0 = 0; ic0 < 256; ic0 += 128) {
        __syncthreads();
#pragma unroll
        for (int j = 0; j < 32; j++) {
            const int idx = t + 256 * j;          // 8192
            const int icl = idx >> 6, xc = idx & 63;
            sm[icl][xc] = x[((size_t)(b * 256 + ic0 + icl) * 64 + y) * 64 + xc];
        }
        __syncthreads();
#pragma unroll
        for (int j = 0; j < 16; j++) {
            const int idx = t + 256 * j;          // 4096 u32
            const int xc = idx >> 6, icp = idx & 63;
            const unsigned short h0 = h16_of(sm[icp * 2][xc]);
            const unsigned short h1 = h16_of(sm[icp * 2 + 1][xc]);
            const unsigned int hw = (unsigned int)h0 | ((unsigned int)h1 << 16);
            const size_t rh = (((size_t)b * 66 + (y + 1)) * 66 + (xc + 1));
            reinterpret_cast<unsigned int*>(g_xt)[rh * 128 + (ic0 >> 1) + icp] = hw;
        }
    }
}

// ===========================================================================
// Kernel 5: mma.sync fp16 GEMM (single pass), cp.async double-buffered,
// 64B swizzled rows.  Grid (ytile 16, phase 4, b 16), 256 thr.
// CTA tile 128 oc x 256 px.
// Per buffer: sx [325 rows][64B] = 20800 (pad 20864) ; sA [4 taps][128][64B] = 32768
// ===========================================================================
#define SA_OFF     20864
#define BUF_STRIDE 54272                          // 20864+32768 padded to 1KB
#define SMEM_BYTES (2 * BUF_STRIDE)               // 108544

__global__ __launch_bounds__(256)
void gemm_kernel(const float* __restrict__ bias,
                 const float* __restrict__ prelu_a,
                 float* __restrict__ out)
{
    extern __shared__ char smem[];
    const uint32_t s0 = smem_u32(smem);

    const int t = threadIdx.x, wid = t >> 5, lane = t & 31;
    const int ytile = blockIdx.x, phase = blockIdx.y, b = blockIdx.z;
    const int py = phase >> 1, px = phase & 1;
    const int y0 = ytile * 4;
    const int dymin = (py == 0) ? -1 : 0;
    const int dxmin = (px == 0) ? -1 : 0;

    const int warp_m = wid & 1;                   // m_base = warp_m*64
    const int warp_n = wid >> 1;                  // output row within tile (0..3)
    const int m_base = warp_m * 64;

    // ldmatrix per-lane addressing
    const int a_row  = lane & 15;
    const int a_coff = lane >> 4;                 // 0/1 -> 16B half within k16
    const int a_sw   = (a_row >> 1) & 3;
    const int b_row  = ((lane >> 4) & 1) * 8 + (lane & 7);
    const int b_coff = (lane >> 3) & 1;

    float acc[4][8][4];
#pragma unroll
    for (int ma = 0; ma < 4; ma++)
#pragma unroll
        for (int j = 0; j < 8; j++)
#pragma unroll
            for (int q = 0; q < 4; q++) acc[ma][j][q] = 0.f;

    const char* gxt = reinterpret_cast<const char*>(g_xt);
    const char* gwt = reinterpret_cast<const char*>(g_wt);

    // ---- staging via cp.async (16B) into swizzled 64B rows -----------------
    auto stage = [&](int ic0, int buf) {
        const uint32_t sb = s0 + buf * BUF_STRIDE;
        for (int i = t; i < 1300; i += 256) {
            const int p = i >> 2, c = i & 3;
            const int jj = p / 65, xi = p - jj * 65;
            const int yy = y0 + dymin + jj + 1;    // in [0,65]
            const int xx = dxmin + xi + 1;         // in [0,65]
            const char* src = gxt
                + (((size_t)b * 66 + yy) * 66 + xx) * 512
                + ic0 * 2 + c * 16;
            cp16(sb + p * 64 + ((c ^ ((p >> 1) & 3)) << 4), src);
        }
        for (int i = t; i < 2048; i += 256) {
            const int c = i & 3, oc = (i >> 2) & 127, tap = i >> 9;
            const int plane = (b * 4 + phase) * 4 + tap;
            const char* src = gwt + (size_t)plane * 65536 + oc * 512
                + ic0 * 2 + c * 16;
            cp16(sb + SA_OFF + tap * 8192 + oc * 64
                 + ((c ^ ((oc >> 1) & 3)) << 4), src);
        }
    };

    stage(0, 0);
    CP_COMMIT();

    for (int chunk = 0; chunk < 8; chunk++) {
        __syncthreads();                          // prior compute done -> safe overwrite
        if (chunk < 7) {
            stage((chunk + 1) * 32, (chunk + 1) & 1);
            CP_COMMIT();
            CP_WAIT(1);                           // chunk's own stage complete
        } else {
            CP_WAIT(0);
        }
        __syncthreads();                          // staged data visible to all

        const uint32_t sb   = s0 + (chunk & 1) * BUF_STRIDE;
        const uint32_t sa_u = sb + SA_OFF;

#pragma unroll
        for (int kk = 0; kk < 2; kk++) {
#pragma unroll
            for (int tap = 0; tap < 4; tap++) {
                const int tky = tap >> 1, tkx = tap & 1;
                const int pbase = (warp_n + 1 - tky) * 65 + (1 - tkx);
                const int brow0 = pbase + b_row;
                const uint32_t boff = brow0 * 64
                    + (((kk * 2 + b_coff) ^ ((brow0 >> 1) & 3)) << 4);
                const uint32_t aoff = (m_base + a_row) * 64
                    + (((kk * 2 + a_coff) ^ a_sw) << 4);

                uint32_t ah[4][4], bh[4][4];
#pragma unroll
                for (int ma = 0; ma < 4; ma++)
                    ldm_x4(ah[ma], sa_u + tap * 8192 + aoff + ma * 1024);
#pragma unroll
                for (int nb = 0; nb < 4; nb++)
                    ldm_x4(bh[nb], sb + boff + nb * 1024);
#pragma unroll
                for (int ma = 0; ma < 4; ma++)
#pragma unroll
                    for (int j = 0; j < 8; j++)
                        mma_fp16(acc[ma][j], ah[ma], bh[j >> 1][(j & 1) * 2],
                                 bh[j >> 1][(j & 1) * 2 + 1]);
            }
        }
    }

    // ---- epilogue: bias + PReLU, scattered stride-2 stores
    const float pa = prelu_a[0];
    const int oy = 2 * (y0 + warp_n) + py;
#pragma unroll
    for (int ma = 0; ma < 4; ma++) {
        const int m0 = m_base + ma * 16 + (lane >> 2);
        const float bz0 = bias[m0];
        const float bz1 = bias[m0 + 8];
        float* r0 = out + ((size_t)(b * COUTC + m0) * OH + oy) * OW + px;
        float* r1 = out + ((size_t)(b * COUTC + m0 + 8) * OH + oy) * OW + px;
#pragma unroll
        for (int j = 0; j < 8; j++) {
            const int col = j * 8 + (lane & 3) * 2;
            float v0 = acc[ma][j][0] + bz0;
            float v1 = acc[ma][j][1] + bz0;
            float v2 = acc[ma][j][2] + bz1;
            float v3 = acc[ma][j][3] + bz1;
            v0 = (v0 >= 0.f) ? v0 : pa * v0;
            v1 = (v1 >= 0.f) ? v1 : pa * v1;
            v2 = (v2 >= 0.f) ? v2 : pa * v2;
            v3 = (v3 >= 0.f) ? v3 : pa * v3;
            r0[2 * col]       = v0;
            r0[2 * (col + 1)] = v1;
            r1[2 * col]       = v2;
            r1[2 * (col + 1)] = v3;
        }
    }
}

// ===========================================================================
extern "C" void kernel_launch(void* const* d_in, const int* in_sizes, int n_in,
                              void* d_out, int out_size)
{
    const float* x       = (const float*)d_in[0];
    const float* feature = (const float*)d_in[1];
    const float* weight  = (const float*)d_in[2];
    const float* tb      = (const float*)d_in[3];
    const float* tq      = (const float*)d_in[4];
    const float* tn      = (const float*)d_in[5];
    const float* tx      = (const float*)d_in[6];
    const float* mb      = (const float*)d_in[7];
    const float* mq      = (const float*)d_in[8];
    const float* mn      = (const float*)d_in[9];
    const float* mx      = (const float*)d_in[10];
    const float* bias    = (const float*)d_in[11];
    const float* prelu_a = (const float*)d_in[12];
    float* out = (float*)d_out;

    cudaFuncSetAttribute(gemm_kernel,
                         cudaFuncAttributeMaxDynamicSharedMemorySize, SMEM_BYTES);

    zero_border_kernel<<<(16 * BORDER_PER_BP + 255) / 256, 256>>>();
    transposeX_kernel<<<1024, 256>>>(x);
    synth_kernel<<<256, 256>>>(feature, weight, tb, tq, tn, tx, mb, mq, mn, mx);
    dim3 gw(256, 4);
    transposeW_kernel<<<gw, 256>>>();

    dim3 grid(16, 4, 16);
    gemm_kernel<<<grid, 256, SMEM_BYTES>>>(bias, prelu_a, out);
}

// round 10
// speedup vs baseline: 6.8343x; 1.0306x over previous
#include <cuda_runtime.h>
#include <cuda_fp16.h>
#include <cstdint>

#define BB   16
#define CINC 256
#define COUTC 128
#define HH   64
#define WW   64
#define OH   128
#define OW   128

// ===========================================================================
// Device scratch (static allocation — allowed)
// g_wi: synthesized fp16 weights, [plane = (b*4+ph)*4+tap][ic 256][oc 128] fp16
// g_wt: transposed,               [plane][oc 128][ic 256] fp16
// g_xt: transposed input,         [b][yy 66][xx 66][ic 256] fp16
// ===========================================================================
__device__ __align__(16) unsigned short g_wi[256u * 256 * 128];
__device__ __align__(16) unsigned short g_wt[256u * 256 * 128];
__device__ __align__(16) unsigned short g_xt[16u * 66 * 66 * 256];

__device__ __forceinline__ unsigned short h16_of(float f) {
    return __half_as_ushort(__float2half_rn(f));
}
__device__ __forceinline__ uint32_t smem_u32(const void* p) {
    uint32_t a;
    asm("{ .reg .u64 tmp; cvta.to.shared.u64 tmp, %1; cvt.u32.u64 %0, tmp; }"
        : "=r"(a) : "l"(p));
    return a;
}
__device__ __forceinline__ void ldm_x4(uint32_t* r, uint32_t addr) {
    asm volatile("ldmatrix.sync.aligned.m8n8.x4.shared.b16 {%0,%1,%2,%3}, [%4];"
                 : "=r"(r[0]), "=r"(r[1]), "=r"(r[2]), "=r"(r[3]) : "r"(addr));
}
__device__ __forceinline__ void mma_fp16(float* c, const uint32_t* a,
                                         uint32_t b0, uint32_t b1) {
    asm volatile("mma.sync.aligned.m16n8k16.row.col.f32.f16.f16.f32 "
                 "{%0,%1,%2,%3}, {%4,%5,%6,%7}, {%8,%9}, {%0,%1,%2,%3};"
                 : "+f"(c[0]), "+f"(c[1]), "+f"(c[2]), "+f"(c[3])
                 : "r"(a[0]), "r"(a[1]), "r"(a[2]), "r"(a[3]), "r"(b0), "r"(b1));
}
__device__ __forceinline__ void cp16(uint32_t saddr, const void* g) {
    asm volatile("cp.async.cg.shared.global [%0], [%1], 16;"
                 :: "r"(saddr), "l"(g) : "memory");
}
#define CP_COMMIT() asm volatile("cp.async.commit_group;" ::: "memory")
#define CP_WAIT(n)  asm volatile("cp.async.wait_group %0;" :: "n"(n) : "memory")

// ===========================================================================
// Kernel 1: weight synthesis (single fp16).  Block per ic.
// ===========================================================================
__global__ __launch_bounds__(256) void synth_kernel(
    const float* __restrict__ feature, const float* __restrict__ w0,
    const float* __restrict__ tb, const float* __restrict__ tq,
    const float* __restrict__ tn, const float* __restrict__ tx,
    const float* __restrict__ mb, const float* __restrict__ mq,
    const float* __restrict__ mn, const float* __restrict__ mx)
{
    __shared__ float sf[64];
    __shared__ float buf[2048];                   // [phase][tap][oc] for one (b, ic)

    const int ic = blockIdx.x;
    const int t  = threadIdx.x;
    if (t < 64) sf[t] = feature[t];
    __syncthreads();

    float base[8], ub[8], uq[8], un[8], ux[8];
    int   sidx[8];
    const int off = ic * 2048;

#pragma unroll
    for (int j = 0; j < 8; j++) {
        const int idx = t + 256 * j;              // = oc*16 + ky*4 + kx
        const int oc  = idx >> 4;
        const int kk  = idx & 15;
        const int ky  = kk >> 2, kx = kk & 3;
        const float mB = mb[ic * COUTC + oc], mQ = mq[ic * COUTC + oc];
        const float mN = mn[ic * COUTC + oc], mX = mx[ic * COUTC + oc];
        base[j] = w0[off + idx];
        ub[j] = tb[off + idx] * mB;
        uq[j] = tq[off + idx] * mQ;
        un[j] = tn[off + idx] * mN;
        ux[j] = tx[off + idx] * mX;
        const int py = 1 - (ky & 1), px = 1 - (kx & 1);
        const int tap = (ky >> 1) * 2 + (kx >> 1);
        sidx[j] = (py * 2 + px) * 512 + tap * 128 + oc;
    }

    for (int b = 0; b < BB; b++) {
        const float f0 = sf[b * 4 + 0], f1 = sf[b * 4 + 1];
        const float f2 = sf[b * 4 + 2], f3 = sf[b * 4 + 3];
#pragma unroll
        for (int j = 0; j < 8; j++)
            buf[sidx[j]] = base[j] + f0 * ub[j] + f1 * uq[j] + f2 * un[j] + f3 * ux[j];
        __syncthreads();
#pragma unroll
        for (int j = 0; j < 8; j++) {
            const int e = t + 256 * j;            // phase*512 + tap*128 + oc
            const int plane = b * 16 + (e >> 7);  // (b*4+phase)*4+tap
            g_wi[(size_t)plane * 32768 + ic * 128 + (e & 127)] = h16_of(buf[e]);
        }
        __syncthreads();
    }
}

// ===========================================================================
// Kernel 2: weight transpose [ic][oc] -> [oc][ic].  Grid (plane 256, icchunk 4)
// ===========================================================================
__global__ __launch_bounds__(256) void transposeW_kernel()
{
    __shared__ unsigned int sm[64][65];
    const int plane = blockIdx.x;
    const int ic0 = blockIdx.y * 64;
    const int t = threadIdx.x;
    const unsigned int* src = reinterpret_cast<const unsigned int*>(g_wi) + (size_t)plane * 16384;
    unsigned int*       dst = reinterpret_cast<unsigned int*>(g_wt) + (size_t)plane * 16384;

#pragma unroll
    for (int j = 0; j < 16; j++) {
        const int idx = t + 256 * j;          // 4096 u32
        const int icl = idx >> 6, oc2 = idx & 63;
        sm[icl][oc2] = src[(ic0 + icl) * 64 + oc2];
    }
    __syncthreads();
#pragma unroll
    for (int j = 0; j < 16; j++) {
        const int idx = t + 256 * j;
        const int oc = idx >> 5, icp = idx & 31;
        const unsigned int w0v = sm[icp * 2][oc >> 1];
        const unsigned int w1v = sm[icp * 2 + 1][oc >> 1];
        const int sh = (oc & 1) * 16;
        const unsigned int r = ((w0v >> sh) & 0xffffu) | (((w1v >> sh) & 0xffffu) << 16);
        dst[oc * 128 + (ic0 >> 1) + icp] = r;
    }
}

// ===========================================================================
// Kernel 3: zero only the halo border of g_xt (interior written by transposeX)
// Split into two launches (bp0 half) so gemm lands on ncu launch index 5.
// ===========================================================================
#define BORDER_PER_BP 8320
__global__ __launch_bounds__(256) void zero_border_kernel(int bp0)
{
    const int idx = blockIdx.x * 256 + threadIdx.x;
    if (idx >= 8 * BORDER_PER_BP) return;
    const int bp = bp0 + idx / BORDER_PER_BP;
    const int r  = idx - (idx / BORDER_PER_BP) * BORDER_PER_BP;
    float4* dst = reinterpret_cast<float4*>(g_xt) + (size_t)bp * 66 * 66 * 32;
    const float4 z = make_float4(0.f, 0.f, 0.f, 0.f);
    if (r < 4224) {
        const int yy  = (r < 2112) ? 0 : 65;
        const int off = (r < 2112) ? r : r - 2112;
        const int pix = off >> 5, c = off & 31;
        dst[((size_t)yy * 66 + pix) * 32 + c] = z;
    } else {
        const int j  = r - 4224;
        const int yy = 1 + (j >> 6);
        const int xx = ((j >> 5) & 1) ? 65 : 0;
        const int c  = j & 31;
        dst[((size_t)yy * 66 + xx) * 32 + c] = z;
    }
}

// ===========================================================================
// Kernel 4: x transpose to fp16: x[b][ic][y][x] -> g_xt[b][y+1][x+1][ic]
// ===========================================================================
__global__ __launch_bounds__(256) void transposeX_kernel(const float* __restrict__ x)
{
    __shared__ float sm[128][65];
    const int bx = blockIdx.x;
    const int b = bx >> 6, y = bx & 63;
    const int t = threadIdx.x;

    for (int ic0 = 0; ic0 < 256; ic0 += 128) {
        __syncthreads();
#pragma unroll
        for (int j = 0; j < 32; j++) {
            const int idx = t + 256 * j;          // 8192
            const int icl = idx >> 6, xc = idx & 63;
            sm[icl][xc] = x[((size_t)(b * 256 + ic0 + icl) * 64 + y) * 64 + xc];
        }
        __syncthreads();
#pragma unroll
        for (int j = 0; j < 16; j++) {
            const int idx = t + 256 * j;          // 4096 u32
            const int xc = idx >> 6, icp = idx & 63;
            const unsigned short h0 = h16_of(sm[icp * 2][xc]);
            const unsigned short h1 = h16_of(sm[icp * 2 + 1][xc]);
            const unsigned int hw = (unsigned int)h0 | ((unsigned int)h1 << 16);
            const size_t rh = (((size_t)b * 66 + (y + 1)) * 66 + (xc + 1));
            reinterpret_cast<unsigned int*>(g_xt)[rh * 128 + (ic0 >> 1) + icp] = hw;
        }
    }
}

// ===========================================================================
// Kernel 5: mma.sync fp16 GEMM (single pass), cp.async 3-stage pipeline,
// 64B swizzled rows.  Grid (ytile 16, phase 4, b 16), 512 thr (16 warps).
// CTA tile 128 oc x 256 px; warp tile 64 oc x 32 px (acc 64 regs).
// Per buffer: sx [325 rows][64B] = 20800 (pad 20864) ; sA [4 taps][128][64B] = 32768
// ===========================================================================
#define SA_OFF     20864
#define BUF_STRIDE 54272                          // 20864+32768 padded to 1KB
#define SMEM_BYTES (3 * BUF_STRIDE)               // 162816

__global__ __launch_bounds__(512, 1)
void gemm_kernel(const float* __restrict__ bias,
                 const float* __restrict__ prelu_a,
                 float* __restrict__ out)
{
    extern __shared__ char smem[];
    const uint32_t s0 = smem_u32(smem);

    const int t = threadIdx.x, wid = t >> 5, lane = t & 31;
    const int ytile = blockIdx.x, phase = blockIdx.y, b = blockIdx.z;
    const int py = phase >> 1, px = phase & 1;
    const int y0 = ytile * 4;
    const int dymin = (py == 0) ? -1 : 0;
    const int dxmin = (px == 0) ? -1 : 0;

    const int warp_m   = wid & 1;                 // m_base = warp_m*64
    const int warp_n   = (wid >> 1) >> 1;         // output row within tile (0..3)
    const int colhalf  = (wid >> 1) & 1;          // 0/1 -> px offset 0/32
    const int m_base = warp_m * 64;
    const int c0     = colhalf * 32;

    // ldmatrix per-lane addressing
    const int a_row  = lane & 15;
    const int a_coff = lane >> 4;                 // 0/1 -> 16B half within k16
    const int a_sw   = (a_row >> 1) & 3;
    const int b_row  = ((lane >> 4) & 1) * 8 + (lane & 7);
    const int b_coff = (lane >> 3) & 1;

    float acc[4][4][4];
#pragma unroll
    for (int ma = 0; ma < 4; ma++)
#pragma unroll
        for (int j = 0; j < 4; j++)
#pragma unroll
            for (int q = 0; q < 4; q++) acc[ma][j][q] = 0.f;

    const char* gxt = reinterpret_cast<const char*>(g_xt);
    const char* gwt = reinterpret_cast<const char*>(g_wt);

    // ---- staging via cp.async (16B) into swizzled 64B rows -----------------
    auto stage = [&](int ic0, int buf) {
        const uint32_t sb = s0 + buf * BUF_STRIDE;
        for (int i = t; i < 1300; i += 512) {
            const int p = i >> 2, c = i & 3;
            const int jj = p / 65, xi = p - jj * 65;
            const int yy = y0 + dymin + jj + 1;    // in [0,65]
            const int xx = dxmin + xi + 1;         // in [0,65]
            const char* src = gxt
                + (((size_t)b * 66 + yy) * 66 + xx) * 512
                + ic0 * 2 + c * 16;
            cp16(sb + p * 64 + ((c ^ ((p >> 1) & 3)) << 4), src);
        }
        for (int i = t; i < 2048; i += 512) {
            const int c = i & 3, oc = (i >> 2) & 127, tap = i >> 9;
            const int plane = (b * 4 + phase) * 4 + tap;
            const char* src = gwt + (size_t)plane * 65536 + oc * 512
                + ic0 * 2 + c * 16;
            cp16(sb + SA_OFF + tap * 8192 + oc * 64
                 + ((c ^ ((oc >> 1) & 3)) << 4), src);
        }
    };

    stage(0, 0);
    CP_COMMIT();
    stage(32, 1);
    CP_COMMIT();

    for (int chunk = 0; chunk < 8; chunk++) {
        CP_WAIT(1);                               // this chunk's data arrived
        __syncthreads();                          // visible + compute(c-1) done
        if (chunk < 6) {
            stage((chunk + 2) * 32, (chunk + 2) % 3);
            CP_COMMIT();
        }

        const uint32_t sb   = s0 + (chunk % 3) * BUF_STRIDE;
        const uint32_t sa_u = sb + SA_OFF;

#pragma unroll
        for (int kk = 0; kk < 2; kk++) {
#pragma unroll
            for (int tap = 0; tap < 4; tap++) {
                const int tky = tap >> 1, tkx = tap & 1;
                const int pbase = (warp_n + 1 - tky) * 65 + (1 - tkx) + c0;
                const int brow0 = pbase + b_row;
                const uint32_t boff = brow0 * 64
                    + (((kk * 2 + b_coff) ^ ((brow0 >> 1) & 3)) << 4);
                const uint32_t aoff = (m_base + a_row) * 64
                    + (((kk * 2 + a_coff) ^ a_sw) << 4);

                uint32_t ah[4][4], bh[2][4];
#pragma unroll
                for (int ma = 0; ma < 4; ma++)
                    ldm_x4(ah[ma], sa_u + tap * 8192 + aoff + ma * 1024);
#pragma unroll
                for (int nb = 0; nb < 2; nb++)
                    ldm_x4(bh[nb], sb + boff + nb * 1024);
#pragma unroll
                for (int ma = 0; ma < 4; ma++)
#pragma unroll
                    for (int j = 0; j < 4; j++)
                        mma_fp16(acc[ma][j], ah[ma], bh[j >> 1][(j & 1) * 2],
                                 bh[j >> 1][(j & 1) * 2 + 1]);
            }
        }
    }

    // ---- epilogue: bias + PReLU, scattered stride-2 stores
    const float pa = prelu_a[0];
    const int oy = 2 * (y0 + warp_n) + py;
#pragma unroll
    for (int ma = 0; ma < 4; ma++) {
        const int m0 = m_base + ma * 16 + (lane >> 2);
        const float bz0 = bias[m0];
        const float bz1 = bias[m0 + 8];
        float* r0 = out + ((size_t)(b * COUTC + m0) * OH + oy) * OW + px;
        float* r1 = out + ((size_t)(b * COUTC + m0 + 8) * OH + oy) * OW + px;
#pragma unroll
        for (int j = 0; j < 4; j++) {
            const int col = c0 + j * 8 + (lane & 3) * 2;
            float v0 = acc[ma][j][0] + bz0;
            float v1 = acc[ma][j][1] + bz0;
            float v2 = acc[ma][j][2] + bz1;
            float v3 = acc[ma][j][3] + bz1;
            v0 = (v0 >= 0.f) ? v0 : pa * v0;
            v1 = (v1 >= 0.f) ? v1 : pa * v1;
            v2 = (v2 >= 0.f) ? v2 : pa * v2;
            v3 = (v3 >= 0.f) ? v3 : pa * v3;
            r0[2 * col]       = v0;
            r0[2 * (col + 1)] = v1;
            r1[2 * col]       = v2;
            r1[2 * (col + 1)] = v3;
        }
    }
}

// ===========================================================================
extern "C" void kernel_launch(void* const* d_in, const int* in_sizes, int n_in,
                              void* d_out, int out_size)
{
    const float* x       = (const float*)d_in[0];
    const float* feature = (const float*)d_in[1];
    const float* weight  = (const float*)d_in[2];
    const float* tb      = (const float*)d_in[3];
    const float* tq      = (const float*)d_in[4];
    const float* tn      = (const float*)d_in[5];
    const float* tx      = (const float*)d_in[6];
    const float* mb      = (const float*)d_in[7];
    const float* mq      = (const float*)d_in[8];
    const float* mn      = (const float*)d_in[9];
    const float* mx      = (const float*)d_in[10];
    const float* bias    = (const float*)d_in[11];
    const float* prelu_a = (const float*)d_in[12];
    float* out = (float*)d_out;

    cudaFuncSetAttribute(gemm_kernel,
                         cudaFuncAttributeMaxDynamicSharedMemorySize, SMEM_BYTES);

    zero_border_kernel<<<(8 * BORDER_PER_BP + 255) / 256, 256>>>(0);   // launch 0
    zero_border_kernel<<<(8 * BORDER_PER_BP + 255) / 256, 256>>>(8);   // launch 1
    transposeX_kernel<<<1024, 256>>>(x);                                // launch 2
    synth_kernel<<<256, 256>>>(feature, weight, tb, tq, tn, tx,         // launch 3
                               mb, mq, mn, mx);
    dim3 gw(256, 4);
    transposeW_kernel<<<gw, 256>>>();                                   // launch 4

    dim3 grid(16, 4, 16);
    gemm_kernel<<<grid, 512, SMEM_BYTES>>>(bias, prelu_a, out);         // launch 5
}

// round 12
// speedup vs baseline: 6.8694x; 1.0051x over previous
#include <cuda_runtime.h>
#include <cuda_fp16.h>
#include <cstdint>

#define BB   16
#define CINC 256
#define COUTC 128
#define HH   64
#define WW   64
#define OH   128
#define OW   128

// ===========================================================================
// Device scratch (static allocation — allowed)
// g_wi: synthesized fp16 weights, [plane = (b*4+ph)*4+tap][ic 256][oc 128] fp16
//       (consumed directly by gemm via ldmatrix.trans — no transpose pass)
// g_xt: transposed input,         [b][yy 66][xx 66][ic 256] fp16
// ===========================================================================
__device__ __align__(16) unsigned short g_wi[256u * 256 * 128];
__device__ __align__(16) unsigned short g_xt[16u * 66 * 66 * 256];

__device__ __forceinline__ unsigned short h16_of(float f) {
    return __half_as_ushort(__float2half_rn(f));
}
__device__ __forceinline__ uint32_t smem_u32(const void* p) {
    uint32_t a;
    asm("{ .reg .u64 tmp; cvta.to.shared.u64 tmp, %1; cvt.u32.u64 %0, tmp; }"
        : "=r"(a) : "l"(p));
    return a;
}
__device__ __forceinline__ void ldm_x4(uint32_t* r, uint32_t addr) {
    asm volatile("ldmatrix.sync.aligned.m8n8.x4.shared.b16 {%0,%1,%2,%3}, [%4];"
                 : "=r"(r[0]), "=r"(r[1]), "=r"(r[2]), "=r"(r[3]) : "r"(addr));
}
__device__ __forceinline__ void ldm_x4_trans(uint32_t* r, uint32_t addr) {
    asm volatile("ldmatrix.sync.aligned.m8n8.x4.trans.shared.b16 {%0,%1,%2,%3}, [%4];"
                 : "=r"(r[0]), "=r"(r[1]), "=r"(r[2]), "=r"(r[3]) : "r"(addr));
}
__device__ __forceinline__ void mma_fp16(float* c, const uint32_t* a,
                                         uint32_t b0, uint32_t b1) {
    asm volatile("mma.sync.aligned.m16n8k16.row.col.f32.f16.f16.f32 "
                 "{%0,%1,%2,%3}, {%4,%5,%6,%7}, {%8,%9}, {%0,%1,%2,%3};"
                 : "+f"(c[0]), "+f"(c[1]), "+f"(c[2]), "+f"(c[3])
                 : "r"(a[0]), "r"(a[1]), "r"(a[2]), "r"(a[3]), "r"(b0), "r"(b1));
}
__device__ __forceinline__ void cp16(uint32_t saddr, const void* g) {
    asm volatile("cp.async.cg.shared.global [%0], [%1], 16;"
                 :: "r"(saddr), "l"(g) : "memory");
}
#define CP_COMMIT() asm volatile("cp.async.commit_group;" ::: "memory")
#define CP_WAIT(n)  asm volatile("cp.async.wait_group %0;" :: "n"(n) : "memory")

// ===========================================================================
// Kernel 1: weight synthesis (single fp16).  Grid (ic 256, bhalf 2);
// each block handles 8 b's -> 2x parallelism (synth was latency-bound).
// ===========================================================================
__global__ __launch_bounds__(256) void synth_kernel(
    const float* __restrict__ feature, const float* __restrict__ w0,
    const float* __restrict__ tb, const float* __restrict__ tq,
    const float* __restrict__ tn, const float* __restrict__ tx,
    const float* __restrict__ mb, const float* __restrict__ mq,
    const float* __restrict__ mn, const float* __restrict__ mx)
{
    __shared__ float sf[64];
    __shared__ float buf[2048];                   // [phase][tap][oc] for one (b, ic)

    const int ic = blockIdx.x;
    const int b0 = blockIdx.y * 8;
    const int t  = threadIdx.x;
    if (t < 64) sf[t] = feature[t];
    __syncthreads();

    float base[8], ub[8], uq[8], un[8], ux[8];
    int   sidx[8];
    const int off = ic * 2048;

#pragma unroll
    for (int j = 0; j < 8; j++) {
        const int idx = t + 256 * j;              // = oc*16 + ky*4 + kx
        const int oc  = idx >> 4;
        const int kk  = idx & 15;
        const int ky  = kk >> 2, kx = kk & 3;
        const float mB = mb[ic * COUTC + oc], mQ = mq[ic * COUTC + oc];
        const float mN = mn[ic * COUTC + oc], mX = mx[ic * COUTC + oc];
        base[j] = w0[off + idx];
        ub[j] = tb[off + idx] * mB;
        uq[j] = tq[off + idx] * mQ;
        un[j] = tn[off + idx] * mN;
        ux[j] = tx[off + idx] * mX;
        const int py = 1 - (ky & 1), px = 1 - (kx & 1);
        const int tap = (ky >> 1) * 2 + (kx >> 1);
        sidx[j] = (py * 2 + px) * 512 + tap * 128 + oc;
    }

    for (int bi = 0; bi < 8; bi++) {
        const int b = b0 + bi;
        const float f0 = sf[b * 4 + 0], f1 = sf[b * 4 + 1];
        const float f2 = sf[b * 4 + 2], f3 = sf[b * 4 + 3];
#pragma unroll
        for (int j = 0; j < 8; j++)
            buf[sidx[j]] = base[j] + f0 * ub[j] + f1 * uq[j] + f2 * un[j] + f3 * ux[j];
        __syncthreads();
#pragma unroll
        for (int j = 0; j < 8; j++) {
            const int e = t + 256 * j;            // phase*512 + tap*128 + oc
            const int plane = b * 16 + (e >> 7);  // (b*4+phase)*4+tap
            g_wi[(size_t)plane * 32768 + ic * 128 + (e & 127)] = h16_of(buf[e]);
        }
        __syncthreads();
    }
}

// ===========================================================================
// Kernel 2: zero only the halo border of g_xt.  (bp0, nbp) launch slices.
// ===========================================================================
#define BORDER_PER_BP 8320
__global__ __launch_bounds__(256) void zero_border_kernel(int bp0, int nbp)
{
    const int idx = blockIdx.x * 256 + threadIdx.x;
    if (idx >= nbp * BORDER_PER_BP) return;
    const int bp = bp0 + idx / BORDER_PER_BP;
    const int r  = idx - (idx / BORDER_PER_BP) * BORDER_PER_BP;
    float4* dst = reinterpret_cast<float4*>(g_xt) + (size_t)bp * 66 * 66 * 32;
    const float4 z = make_float4(0.f, 0.f, 0.f, 0.f);
    if (r < 4224) {
        const int yy  = (r < 2112) ? 0 : 65;
        const int off = (r < 2112) ? r : r - 2112;
        const int pix = off >> 5, c = off & 31;
        dst[((size_t)yy * 66 + pix) * 32 + c] = z;
    } else {
        const int j  = r - 4224;
        const int yy = 1 + (j >> 6);
        const int xx = ((j >> 5) & 1) ? 65 : 0;
        const int c  = j & 31;
        dst[((size_t)yy * 66 + xx) * 32 + c] = z;
    }
}

// ===========================================================================
// Kernel 3: x transpose to fp16: x[b][ic][y][x] -> g_xt[b][y+1][x+1][ic]
// ===========================================================================
__global__ __launch_bounds__(256) void transposeX_kernel(const float* __restrict__ x)
{
    __shared__ float sm[128][65];
    const int bx = blockIdx.x;
    const int b = bx >> 6, y = bx & 63;
    const int t = threadIdx.x;

    for (int ic0 = 0; ic0 < 256; ic0 += 128) {
        __syncthreads();
#pragma unroll
        for (int j = 0; j < 32; j++) {
            const int idx = t + 256 * j;          // 8192
            const int icl = idx >> 6, xc = idx & 63;
            sm[icl][xc] = x[((size_t)(b * 256 + ic0 + icl) * 64 + y) * 64 + xc];
        }
        __syncthreads();
#pragma unroll
        for (int j = 0; j < 16; j++) {
            const int idx = t + 256 * j;          // 4096 u32
            const int xc = idx >> 6, icp = idx & 63;
            const unsigned short h0 = h16_of(sm[icp * 2][xc]);
            const unsigned short h1 = h16_of(sm[icp * 2 + 1][xc]);
            const unsigned int hw = (unsigned int)h0 | ((unsigned int)h1 << 16);
            const size_t rh = (((size_t)b * 66 + (y + 1)) * 66 + (xc + 1));
            reinterpret_cast<unsigned int*>(g_xt)[rh * 128 + (ic0 >> 1) + icp] = hw;
        }
    }
}

// ===========================================================================
// Kernel 4: mma.sync fp16 GEMM (single pass), cp.async 3-stage pipeline.
// A loaded via ldmatrix.trans from [ic][oc] layout (no weight transpose pass).
// Grid (ytile 16, phase 4, b 16), 512 thr (16 warps).
// CTA tile 128 oc x 256 px; warp tile 64 oc x 32 px (acc 64 regs).
// Per buffer: sx [325 rows][64B] = 20800 (pad 20864);
//             sA [4 taps][32 ic rows][256B] = 32768  (XOR-swizzled by ic&7)
// ===========================================================================
#define SA_OFF     20864
#define BUF_STRIDE 54272                          // 20864+32768 padded to 1KB
#define SMEM_BYTES (3 * BUF_STRIDE)               // 162816

__global__ __launch_bounds__(512, 1)
void gemm_kernel(const float* __restrict__ bias,
                 const float* __restrict__ prelu_a,
                 float* __restrict__ out)
{
    extern __shared__ char smem[];
    const uint32_t s0 = smem_u32(smem);

    const int t = threadIdx.x, wid = t >> 5, lane = t & 31;
    const int ytile = blockIdx.x, phase = blockIdx.y, b = blockIdx.z;
    const int py = phase >> 1, px = phase & 1;
    const int y0 = ytile * 4;
    const int dymin = (py == 0) ? -1 : 0;
    const int dxmin = (px == 0) ? -1 : 0;

    const int warp_m   = wid & 1;                 // m_base = warp_m*64
    const int warp_n   = (wid >> 1) >> 1;         // output row within tile (0..3)
    const int colhalf  = (wid >> 1) & 1;          // 0/1 -> px offset 0/32
    const int m_base = warp_m * 64;
    const int c0     = colhalf * 32;

    // ldmatrix.trans per-lane addressing for A (source rows = ic, cols = oc):
    const int a_krow  = ((lane >> 4) & 1) * 8 + (lane & 7);
    const int a_mcol8 = (lane >> 3) & 1;
    // ldmatrix (non-trans) per-lane addressing for B
    const int b_row  = ((lane >> 4) & 1) * 8 + (lane & 7);
    const int b_coff = (lane >> 3) & 1;

    float acc[4][4][4];
#pragma unroll
    for (int ma = 0; ma < 4; ma++)
#pragma unroll
        for (int j = 0; j < 4; j++)
#pragma unroll
            for (int q = 0; q < 4; q++) acc[ma][j][q] = 0.f;

    const char* gxt = reinterpret_cast<const char*>(g_xt);
    const char* gwi = reinterpret_cast<const char*>(g_wi);

    // ---- staging via cp.async (16B) ---------------------------------------
    auto stage = [&](int ic0, int buf) {
        const uint32_t sb = s0 + buf * BUF_STRIDE;
        for (int i = t; i < 1300; i += 512) {
            const int p = i >> 2, c = i & 3;
            const int jj = p / 65, xi = p - jj * 65;
            const int yy = y0 + dymin + jj + 1;    // in [0,65]
            const int xx = dxmin + xi + 1;         // in [0,65]
            const char* src = gxt
                + (((size_t)b * 66 + yy) * 66 + xx) * 512
                + ic0 * 2 + c * 16;
            cp16(sb + p * 64 + ((c ^ ((p >> 1) & 3)) << 4), src);
        }
        // A: per tap, contiguous 8KB block [32 ic][128 oc] from g_wi
        for (int i = t; i < 2048; i += 512) {
            const int c = i & 15, icl = (i >> 4) & 31, tap = i >> 9;
            const int plane = (b * 4 + phase) * 4 + tap;
            const char* src = gwi + (size_t)plane * 65536
                + (ic0 + icl) * 256 + c * 16;
            cp16(sb + SA_OFF + tap * 8192 + icl * 256
                 + ((c ^ (icl & 7)) << 4), src);
        }
    };

    stage(0, 0);
    CP_COMMIT();
    stage(32, 1);
    CP_COMMIT();

    for (int chunk = 0; chunk < 8; chunk++) {
        CP_WAIT(1);                               // this chunk's data arrived
        __syncthreads();                          // visible + compute(c-1) done
        if (chunk < 6) {
            stage((chunk + 2) * 32, (chunk + 2) % 3);
            CP_COMMIT();
        }

        const uint32_t sb   = s0 + (chunk % 3) * BUF_STRIDE;
        const uint32_t sa_u = sb + SA_OFF;

#pragma unroll
        for (int kk = 0; kk < 2; kk++) {
#pragma unroll
            for (int tap = 0; tap < 4; tap++) {
                const int tky = tap >> 1, tkx = tap & 1;
                const int pbase = (warp_n + 1 - tky) * 65 + (1 - tkx) + c0;
                const int brow0 = pbase + b_row;
                const uint32_t boff = brow0 * 64
                    + (((kk * 2 + b_coff) ^ ((brow0 >> 1) & 3)) << 4);
                // A trans-load: row = kk*16 + a_krow (256B rows), col16 xor ic&7
                const int arow = kk * 16 + a_krow;
                const uint32_t abase = sa_u + tap * 8192 + arow * 256;

                uint32_t ah[4][4], bh[2][4];
#pragma unroll
                for (int ma = 0; ma < 4; ma++) {
                    const int col16 = (m_base >> 3) + (ma << 1) + a_mcol8;
                    ldm_x4_trans(ah[ma], abase + ((col16 ^ (a_krow & 7)) << 4));
                }
#pragma unroll
                for (int nb = 0; nb < 2; nb++)
                    ldm_x4(bh[nb], sb + boff + nb * 1024);
#pragma unroll
                for (int ma = 0; ma < 4; ma++)
#pragma unroll
                    for (int j = 0; j < 4; j++)
                        mma_fp16(acc[ma][j], ah[ma], bh[j >> 1][(j & 1) * 2],
                                 bh[j >> 1][(j & 1) * 2 + 1]);
            }
        }
    }

    // ---- epilogue: bias + PReLU, scattered stride-2 stores
    const float pa = prelu_a[0];
    const int oy = 2 * (y0 + warp_n) + py;
#pragma unroll
    for (int ma = 0; ma < 4; ma++) {
        const int m0 = m_base + ma * 16 + (lane >> 2);
        const float bz0 = bias[m0];
        const float bz1 = bias[m0 + 8];
        float* r0 = out + ((size_t)(b * COUTC + m0) * OH + oy) * OW + px;
        float* r1 = out + ((size_t)(b * COUTC + m0 + 8) * OH + oy) * OW + px;
#pragma unroll
        for (int j = 0; j < 4; j++) {
            const int col = c0 + j * 8 + (lane & 3) * 2;
            float v0 = acc[ma][j][0] + bz0;
            float v1 = acc[ma][j][1] + bz0;
            float v2 = acc[ma][j][2] + bz1;
            float v3 = acc[ma][j][3] + bz1;
            v0 = (v0 >= 0.f) ? v0 : pa * v0;
            v1 = (v1 >= 0.f) ? v1 : pa * v1;
            v2 = (v2 >= 0.f) ? v2 : pa * v2;
            v3 = (v3 >= 0.f) ? v3 : pa * v3;
            r0[2 * col]       = v0;
            r0[2 * (col + 1)] = v1;
            r1[2 * col]       = v2;
            r1[2 * (col + 1)] = v3;
        }
    }
}

// ===========================================================================
extern "C" void kernel_launch(void* const* d_in, const int* in_sizes, int n_in,
                              void* d_out, int out_size)
{
    const float* x       = (const float*)d_in[0];
    const float* feature = (const float*)d_in[1];
    const float* weight  = (const float*)d_in[2];
    const float* tb      = (const float*)d_in[3];
    const float* tq      = (const float*)d_in[4];
    const float* tn      = (const float*)d_in[5];
    const float* tx      = (const float*)d_in[6];
    const float* mb      = (const float*)d_in[7];
    const float* mq      = (const float*)d_in[8];
    const float* mn      = (const float*)d_in[9];
    const float* mx      = (const float*)d_in[10];
    const float* bias    = (const float*)d_in[11];
    const float* prelu_a = (const float*)d_in[12];
    float* out = (float*)d_out;

    cudaFuncSetAttribute(gemm_kernel,
                         cudaFuncAttributeMaxDynamicSharedMemorySize, SMEM_BYTES);

    zero_border_kernel<<<(6 * BORDER_PER_BP + 255) / 256, 256>>>(0, 6);   // 0
    zero_border_kernel<<<(6 * BORDER_PER_BP + 255) / 256, 256>>>(6, 6);   // 1
    zero_border_kernel<<<(4 * BORDER_PER_BP + 255) / 256, 256>>>(12, 4);  // 2
    transposeX_kernel<<<1024, 256>>>(x);                                  // 3
    dim3 gs(256, 2);
    synth_kernel<<<gs, 256>>>(feature, weight, tb, tq, tn, tx,            // 4
                              mb, mq, mn, mx);

    dim3 grid(16, 4, 16);
    gemm_kernel<<<grid, 512, SMEM_BYTES>>>(bias, prelu_a, out);           // 5
}

// round 14
// speedup vs baseline: 8.1638x; 1.1884x over previous
#include <cuda_runtime.h>
#include <cuda_fp16.h>
#include <cstdint>

#define BB   16
#define CINC 256
#define COUTC 128
#define HH   64
#define WW   64
#define OH   128
#define OW   128

// ===========================================================================
// Device scratch (static allocation — allowed)
// g_wi: synthesized fp16 weights, [plane = (b*4+ph)*4+tap][ic 256][oc 128] fp16
//       (consumed directly by gemm via ldmatrix.trans — no transpose pass)
// g_xt: transposed input,         [b][yy 66][xx 66][ic 256] fp16
// ===========================================================================
__device__ __align__(16) unsigned short g_wi[256u * 256 * 128];
__device__ __align__(16) unsigned short g_xt[16u * 66 * 66 * 256];

__device__ __forceinline__ unsigned short h16_of(float f) {
    return __half_as_ushort(__float2half_rn(f));
}
__device__ __forceinline__ uint32_t smem_u32(const void* p) {
    uint32_t a;
    asm("{ .reg .u64 tmp; cvta.to.shared.u64 tmp, %1; cvt.u32.u64 %0, tmp; }"
        : "=r"(a) : "l"(p));
    return a;
}
__device__ __forceinline__ void ldm_x4(uint32_t* r, uint32_t addr) {
    asm volatile("ldmatrix.sync.aligned.m8n8.x4.shared.b16 {%0,%1,%2,%3}, [%4];"
                 : "=r"(r[0]), "=r"(r[1]), "=r"(r[2]), "=r"(r[3]) : "r"(addr));
}
__device__ __forceinline__ void ldm_x4_trans(uint32_t* r, uint32_t addr) {
    asm volatile("ldmatrix.sync.aligned.m8n8.x4.trans.shared.b16 {%0,%1,%2,%3}, [%4];"
                 : "=r"(r[0]), "=r"(r[1]), "=r"(r[2]), "=r"(r[3]) : "r"(addr));
}
__device__ __forceinline__ void mma_fp16(float* c, const uint32_t* a,
                                         uint32_t b0, uint32_t b1) {
    asm volatile("mma.sync.aligned.m16n8k16.row.col.f32.f16.f16.f32 "
                 "{%0,%1,%2,%3}, {%4,%5,%6,%7}, {%8,%9}, {%0,%1,%2,%3};"
                 : "+f"(c[0]), "+f"(c[1]), "+f"(c[2]), "+f"(c[3])
                 : "r"(a[0]), "r"(a[1]), "r"(a[2]), "r"(a[3]), "r"(b0), "r"(b1));
}
__device__ __forceinline__ void cp16(uint32_t saddr, const void* g) {
    asm volatile("cp.async.cg.shared.global [%0], [%1], 16;"
                 :: "r"(saddr), "l"(g) : "memory");
}
#define CP_COMMIT() asm volatile("cp.async.commit_group;" ::: "memory")
#define CP_WAIT(n)  asm volatile("cp.async.wait_group %0;" :: "n"(n) : "memory")

// ===========================================================================
// Kernel 1: weight synthesis (single fp16).  Grid (ic 256, bhalf 2);
// each block handles 8 b's.
// ===========================================================================
__global__ __launch_bounds__(256) void synth_kernel(
    const float* __restrict__ feature, const float* __restrict__ w0,
    const float* __restrict__ tb, const float* __restrict__ tq,
    const float* __restrict__ tn, const float* __restrict__ tx,
    const float* __restrict__ mb, const float* __restrict__ mq,
    const float* __restrict__ mn, const float* __restrict__ mx)
{
    __shared__ float sf[64];
    __shared__ float buf[2048];                   // [phase][tap][oc] for one (b, ic)

    const int ic = blockIdx.x;
    const int b0 = blockIdx.y * 8;
    const int t  = threadIdx.x;
    if (t < 64) sf[t] = feature[t];
    __syncthreads();

    float base[8], ub[8], uq[8], un[8], ux[8];
    int   sidx[8];
    const int off = ic * 2048;

#pragma unroll
    for (int j = 0; j < 8; j++) {
        const int idx = t + 256 * j;              // = oc*16 + ky*4 + kx
        const int oc  = idx >> 4;
        const int kk  = idx & 15;
        const int ky  = kk >> 2, kx = kk & 3;
        const float mB = mb[ic * COUTC + oc], mQ = mq[ic * COUTC + oc];
        const float mN = mn[ic * COUTC + oc], mX = mx[ic * COUTC + oc];
        base[j] = w0[off + idx];
        ub[j] = tb[off + idx] * mB;
        uq[j] = tq[off + idx] * mQ;
        un[j] = tn[off + idx] * mN;
        ux[j] = tx[off + idx] * mX;
        const int py = 1 - (ky & 1), px = 1 - (kx & 1);
        const int tap = (ky >> 1) * 2 + (kx >> 1);
        sidx[j] = (py * 2 + px) * 512 + tap * 128 + oc;
    }

    for (int bi = 0; bi < 8; bi++) {
        const int b = b0 + bi;
        const float f0 = sf[b * 4 + 0], f1 = sf[b * 4 + 1];
        const float f2 = sf[b * 4 + 2], f3 = sf[b * 4 + 3];
#pragma unroll
        for (int j = 0; j < 8; j++)
            buf[sidx[j]] = base[j] + f0 * ub[j] + f1 * uq[j] + f2 * un[j] + f3 * ux[j];
        __syncthreads();
#pragma unroll
        for (int j = 0; j < 8; j++) {
            const int e = t + 256 * j;            // phase*512 + tap*128 + oc
            const int plane = b * 16 + (e >> 7);  // (b*4+phase)*4+tap
            g_wi[(size_t)plane * 32768 + ic * 128 + (e & 127)] = h16_of(buf[e]);
        }
        __syncthreads();
    }
}

// ===========================================================================
// Kernel 2: zero only the halo border of g_xt.  (bp0, nbp) launch slices.
// ===========================================================================
#define BORDER_PER_BP 8320
__global__ __launch_bounds__(256) void zero_border_kernel(int bp0, int nbp)
{
    const int idx = blockIdx.x * 256 + threadIdx.x;
    if (idx >= nbp * BORDER_PER_BP) return;
    const int bp = bp0 + idx / BORDER_PER_BP;
    const int r  = idx - (idx / BORDER_PER_BP) * BORDER_PER_BP;
    float4* dst = reinterpret_cast<float4*>(g_xt) + (size_t)bp * 66 * 66 * 32;
    const float4 z = make_float4(0.f, 0.f, 0.f, 0.f);
    if (r < 4224) {
        const int yy  = (r < 2112) ? 0 : 65;
        const int off = (r < 2112) ? r : r - 2112;
        const int pix = off >> 5, c = off & 31;
        dst[((size_t)yy * 66 + pix) * 32 + c] = z;
    } else {
        const int j  = r - 4224;
        const int yy = 1 + (j >> 6);
        const int xx = ((j >> 5) & 1) ? 65 : 0;
        const int c  = j & 31;
        dst[((size_t)yy * 66 + xx) * 32 + c] = z;
    }
}

// ===========================================================================
// Kernel 3: x transpose to fp16: x[b][ic][y][x] -> g_xt[b][y+1][x+1][ic]
// Grid (y 64, b 16, icq 4): each block does a 64-ic x 64-x slab.
// 4x finer than R12 (transposeX was latency-bound: issue 12.8%, occ 23.8%).
// ===========================================================================
__global__ __launch_bounds__(256) void transposeX_kernel(const float* __restrict__ x)
{
    __shared__ float sm[64][65];
    const int y   = blockIdx.x;
    const int b   = blockIdx.y;
    const int ic0 = blockIdx.z * 64;
    const int t   = threadIdx.x;

#pragma unroll
    for (int j = 0; j < 16; j++) {
        const int idx = t + 256 * j;              // 4096
        const int icl = idx >> 6, xc = idx & 63;
        sm[icl][xc] = x[((size_t)(b * 256 + ic0 + icl) * 64 + y) * 64 + xc];
    }
    __syncthreads();
#pragma unroll
    for (int j = 0; j < 8; j++) {
        const int idx = t + 256 * j;              // 2048 u32
        const int xc = idx >> 5, icp = idx & 31;
        const unsigned short h0 = h16_of(sm[icp * 2][xc]);
        const unsigned short h1 = h16_of(sm[icp * 2 + 1][xc]);
        const unsigned int hw = (unsigned int)h0 | ((unsigned int)h1 << 16);
        const size_t rh = (((size_t)b * 66 + (y + 1)) * 66 + (xc + 1));
        reinterpret_cast<unsigned int*>(g_xt)[rh * 128 + (ic0 >> 1) + icp] = hw;
    }
}

// ===========================================================================
// Kernel 4: mma.sync fp16 GEMM (single pass), cp.async 3-stage pipeline.
// A loaded via ldmatrix.trans from [ic][oc] layout (no weight transpose pass).
// Grid (ytile 16, phase 4, b 16), 512 thr (16 warps).
// CTA tile 128 oc x 256 px; warp tile 64 oc x 32 px (acc 64 regs).
// Per buffer: sx [325 rows][64B] = 20800 (pad 20864);
//             sA [4 taps][32 ic rows][256B] = 32768  (XOR-swizzled by ic&7)
// ===========================================================================
#define SA_OFF     20864
#define BUF_STRIDE 54272                          // 20864+32768 padded to 1KB
#define SMEM_BYTES (3 * BUF_STRIDE)               // 162816

__global__ __launch_bounds__(512, 1)
void gemm_kernel(const float* __restrict__ bias,
                 const float* __restrict__ prelu_a,
                 float* __restrict__ out)
{
    extern __shared__ char smem[];
    const uint32_t s0 = smem_u32(smem);

    const int t = threadIdx.x, wid = t >> 5, lane = t & 31;
    const int ytile = blockIdx.x, phase = blockIdx.y, b = blockIdx.z;
    const int py = phase >> 1, px = phase & 1;
    const int y0 = ytile * 4;
    const int dymin = (py == 0) ? -1 : 0;
    const int dxmin = (px == 0) ? -1 : 0;

    const int warp_m   = wid & 1;                 // m_base = warp_m*64
    const int warp_n   = (wid >> 1) >> 1;         // output row within tile (0..3)
    const int colhalf  = (wid >> 1) & 1;          // 0/1 -> px offset 0/32
    const int m_base = warp_m * 64;
    const int c0     = colhalf * 32;

    // ldmatrix.trans per-lane addressing for A (source rows = ic, cols = oc):
    const int a_krow  = ((lane >> 4) & 1) * 8 + (lane & 7);
    const int a_mcol8 = (lane >> 3) & 1;
    // ldmatrix (non-trans) per-lane addressing for B
    const int b_row  = ((lane >> 4) & 1) * 8 + (lane & 7);
    const int b_coff = (lane >> 3) & 1;

    float acc[4][4][4];
#pragma unroll
    for (int ma = 0; ma < 4; ma++)
#pragma unroll
        for (int j = 0; j < 4; j++)
#pragma unroll
            for (int q = 0; q < 4; q++) acc[ma][j][q] = 0.f;

    const char* gxt = reinterpret_cast<const char*>(g_xt);
    const char* gwi = reinterpret_cast<const char*>(g_wi);

    // ---- staging via cp.async (16B) ---------------------------------------
    auto stage = [&](int ic0, int buf) {
        const uint32_t sb = s0 + buf * BUF_STRIDE;
        for (int i = t; i < 1300; i += 512) {
            const int p = i >> 2, c = i & 3;
            const int jj = p / 65, xi = p - jj * 65;
            const int yy = y0 + dymin + jj + 1;    // in [0,65]
            const int xx = dxmin + xi + 1;         // in [0,65]
            const char* src = gxt
                + (((size_t)b * 66 + yy) * 66 + xx) * 512
                + ic0 * 2 + c * 16;
            cp16(sb + p * 64 + ((c ^ ((p >> 1) & 3)) << 4), src);
        }
        // A: per tap, contiguous 8KB block [32 ic][128 oc] from g_wi
        for (int i = t; i < 2048; i += 512) {
            const int c = i & 15, icl = (i >> 4) & 31, tap = i >> 9;
            const int plane = (b * 4 + phase) * 4 + tap;
            const char* src = gwi + (size_t)plane * 65536
                + (ic0 + icl) * 256 + c * 16;
            cp16(sb + SA_OFF + tap * 8192 + icl * 256
                 + ((c ^ (icl & 7)) << 4), src);
        }
    };

    stage(0, 0);
    CP_COMMIT();
    stage(32, 1);
    CP_COMMIT();

    for (int chunk = 0; chunk < 8; chunk++) {
        CP_WAIT(1);                               // this chunk's data arrived
        __syncthreads();                          // visible + compute(c-1) done
        if (chunk < 6) {
            stage((chunk + 2) * 32, (chunk + 2) % 3);
            CP_COMMIT();
        }

        const uint32_t sb   = s0 + (chunk % 3) * BUF_STRIDE;
        const uint32_t sa_u = sb + SA_OFF;

#pragma unroll
        for (int kk = 0; kk < 2; kk++) {
#pragma unroll
            for (int tap = 0; tap < 4; tap++) {
                const int tky = tap >> 1, tkx = tap & 1;
                const int pbase = (warp_n + 1 - tky) * 65 + (1 - tkx) + c0;
                const int brow0 = pbase + b_row;
                const uint32_t boff = brow0 * 64
                    + (((kk * 2 + b_coff) ^ ((brow0 >> 1) & 3)) << 4);
                // A trans-load: row = kk*16 + a_krow (256B rows), col16 xor ic&7
                const int arow = kk * 16 + a_krow;
                const uint32_t abase = sa_u + tap * 8192 + arow * 256;

                uint32_t ah[4][4], bh[2][4];
#pragma unroll
                for (int ma = 0; ma < 4; ma++) {
                    const int col16 = (m_base >> 3) + (ma << 1) + a_mcol8;
                    ldm_x4_trans(ah[ma], abase + ((col16 ^ (a_krow & 7)) << 4));
                }
#pragma unroll
                for (int nb = 0; nb < 2; nb++)
                    ldm_x4(bh[nb], sb + boff + nb * 1024);
#pragma unroll
                for (int ma = 0; ma < 4; ma++)
#pragma unroll
                    for (int j = 0; j < 4; j++)
                        mma_fp16(acc[ma][j], ah[ma], bh[j >> 1][(j & 1) * 2],
                                 bh[j >> 1][(j & 1) * 2 + 1]);
            }
        }
    }

    // ---- epilogue: bias + PReLU, scattered stride-2 stores
    const float pa = prelu_a[0];
    const int oy = 2 * (y0 + warp_n) + py;
#pragma unroll
    for (int ma = 0; ma < 4; ma++) {
        const int m0 = m_base + ma * 16 + (lane >> 2);
        const float bz0 = bias[m0];
        const float bz1 = bias[m0 + 8];
        float* r0 = out + ((size_t)(b * COUTC + m0) * OH + oy) * OW + px;
        float* r1 = out + ((size_t)(b * COUTC + m0 + 8) * OH + oy) * OW + px;
#pragma unroll
        for (int j = 0; j < 4; j++) {
            const int col = c0 + j * 8 + (lane & 3) * 2;
            float v0 = acc[ma][j][0] + bz0;
            float v1 = acc[ma][j][1] + bz0;
            float v2 = acc[ma][j][2] + bz1;
            float v3 = acc[ma][j][3] + bz1;
            v0 = (v0 >= 0.f) ? v0 : pa * v0;
            v1 = (v1 >= 0.f) ? v1 : pa * v1;
            v2 = (v2 >= 0.f) ? v2 : pa * v2;
            v3 = (v3 >= 0.f) ? v3 : pa * v3;
            r0[2 * col]       = v0;
            r0[2 * (col + 1)] = v1;
            r1[2 * col]       = v2;
            r1[2 * (col + 1)] = v3;
        }
    }
}

// ===========================================================================
extern "C" void kernel_launch(void* const* d_in, const int* in_sizes, int n_in,
                              void* d_out, int out_size)
{
    const float* x       = (const float*)d_in[0];
    const float* feature = (const float*)d_in[1];
    const float* weight  = (const float*)d_in[2];
    const float* tb      = (const float*)d_in[3];
    const float* tq      = (const float*)d_in[4];
    const float* tn      = (const float*)d_in[5];
    const float* tx      = (const float*)d_in[6];
    const float* mb      = (const float*)d_in[7];
    const float* mq      = (const float*)d_in[8];
    const float* mn      = (const float*)d_in[9];
    const float* mx      = (const float*)d_in[10];
    const float* bias    = (const float*)d_in[11];
    const float* prelu_a = (const float*)d_in[12];
    float* out = (float*)d_out;

    cudaFuncSetAttribute(gemm_kernel,
                         cudaFuncAttributeMaxDynamicSharedMemorySize, SMEM_BYTES);

    zero_border_kernel<<<(6 * BORDER_PER_BP + 255) / 256, 256>>>(0, 6);   // 0
    zero_border_kernel<<<(6 * BORDER_PER_BP + 255) / 256, 256>>>(6, 6);   // 1
    zero_border_kernel<<<(4 * BORDER_PER_BP + 255) / 256, 256>>>(12, 4);  // 2
    dim3 gx(64, 16, 4);
    transposeX_kernel<<<gx, 256>>>(x);                                    // 3
    dim3 gs(256, 2);
    synth_kernel<<<gs, 256>>>(feature, weight, tb, tq, tn, tx,            // 4
                              mb, mq, mn, mx);

    dim3 grid(16, 4, 16);
    gemm_kernel<<<grid, 512, SMEM_BYTES>>>(bias, prelu_a, out);           // 5
}